// round 4
// baseline (speedup 1.0000x reference)
#include <cuda_runtime.h>
#include <math.h>
#include <stdint.h>

#define SEQ    4096
#define DMODEL 1024
#define NH     16
#define HS     64

// Scratch (no cudaMalloc allowed). All hold tf32-rounded fp32 bit patterns.
__device__ float g_x[SEQ * DMODEL];
__device__ float g_wqkv[3 * DMODEL * DMODEL];
__device__ float g_wo[DMODEL * DMODEL];
__device__ float g_Q[NH * SEQ * HS];
__device__ float g_K[NH * SEQ * HS];
__device__ float g_V[NH * SEQ * HS];
__device__ float g_attn[SEQ * DMODEL];

__device__ __forceinline__ uint32_t f2tf32(float x) {
    uint32_t r;
    asm("cvt.rna.tf32.f32 %0, %1;" : "=r"(r) : "f"(x));
    return r;
}
__device__ __forceinline__ float tf32f(float x) {
    return __uint_as_float(f2tf32(x));
}
__device__ __forceinline__ uint32_t fu(float x) { return __float_as_uint(x); }

__device__ __forceinline__ void mma8(float* c,
    uint32_t a0, uint32_t a1, uint32_t a2, uint32_t a3,
    uint32_t b0, uint32_t b1)
{
    asm volatile(
        "mma.sync.aligned.m16n8k8.row.col.f32.tf32.tf32.f32 "
        "{%0,%1,%2,%3},{%4,%5,%6,%7},{%8,%9},{%0,%1,%2,%3};"
        : "+f"(c[0]), "+f"(c[1]), "+f"(c[2]), "+f"(c[3])
        : "r"(a0), "r"(a1), "r"(a2), "r"(a3), "r"(b0), "r"(b1));
}

__device__ __forceinline__ void cp16(uint32_t saddr, const void* gptr) {
    asm volatile("cp.async.cg.shared.global [%0], [%1], 16;"
                 :: "r"(saddr), "l"(gptr));
}
__device__ __forceinline__ uint32_t s2u(const void* p) {
    return (uint32_t)__cvta_generic_to_shared(p);
}
#define CP_COMMIT()  asm volatile("cp.async.commit_group;")
#define CP_WAIT1()   asm volatile("cp.async.wait_group 1;")
#define CP_WAIT0()   asm volatile("cp.async.wait_group 0;")

// ---------------------------------------------------------------------------
// Pre-pass: round x, w_qkv, w_o to tf32 once. Memory-bound, ~64 MB traffic.
// ---------------------------------------------------------------------------
__global__ __launch_bounds__(512) void prepass(
    const float* __restrict__ x, const float* __restrict__ wqkv,
    const float* __restrict__ wo)
{
    const int N4x = (SEQ * DMODEL) / 4;          // 1048576
    const int N4q = (3 * DMODEL * DMODEL) / 4;   // 786432
    const int N4o = (DMODEL * DMODEL) / 4;       // 262144
    int i = blockIdx.x * blockDim.x + threadIdx.x;
    const int total = N4x + N4q + N4o;
    for (; i < total; i += gridDim.x * blockDim.x) {
        const float4* src; float4* dst; int k;
        if (i < N4x)            { src = (const float4*)x;    dst = (float4*)g_x;    k = i; }
        else if (i < N4x + N4q) { src = (const float4*)wqkv; dst = (float4*)g_wqkv; k = i - N4x; }
        else                    { src = (const float4*)wo;   dst = (float4*)g_wo;   k = i - N4x - N4q; }
        float4 v = src[k];
        v.x = tf32f(v.x); v.y = tf32f(v.y); v.z = tf32f(v.z); v.w = tf32f(v.w);
        dst[k] = v;
    }
}

// ---------------------------------------------------------------------------
// tf32 tensor-core GEMM, cp.async 2-stage pipeline.
// C[M,N] = A[M,1024] * B[N,1024]^T + bias[N]
// MODE 0: A = g_x,    B = g_wqkv, scatter tf32 into g_Q/g_K/g_V (N = 3072)
// MODE 1: A = g_attn, B = g_wo,   write fp32 C = d_out (N = 1024)
// 128x128 block, BK=32, 256 threads (8 warps), warp tile 64x32.
// ---------------------------------------------------------------------------
#define GTILE  (128 * 36)            // floats, one operand tile (stride 36)
#define GSTAGE (2 * GTILE)           // As + Bs
#define GEMM_SMEM (2 * GSTAGE * 4)   // 2 stages, bytes = 73728

template <int MODE>
__device__ __forceinline__ void gemm_issue(float* sm, int s, int bm, int bn,
                                           int k0, int t)
{
    const float* __restrict__ Asrc = (MODE == 0) ? g_x    : g_attn;
    const float* __restrict__ Bsrc = (MODE == 0) ? g_wqkv : g_wo;
    float* As = sm + s * GSTAGE;
    float* Bs = As + GTILE;
#pragma unroll
    for (int j = 0; j < 4; j++) {
        int idx = t + j * 256;
        int row = idx >> 3;
        int col = (idx & 7) * 4;
        cp16(s2u(As + row * 36 + col),
             Asrc + (size_t)(bm + row) * DMODEL + k0 + col);
        cp16(s2u(Bs + row * 36 + col),
             Bsrc + (size_t)(bn + row) * DMODEL + k0 + col);
    }
    CP_COMMIT();
}

template <int MODE>
__global__ __launch_bounds__(256) void gemm_tc(
    const float* __restrict__ bias, float* __restrict__ C)
{
    extern __shared__ float sm[];
    const int bm = blockIdx.y * 128;
    const int bn = blockIdx.x * 128;
    const int t    = threadIdx.x;
    const int warp = t >> 5;
    const int lane = t & 31;
    const int wm = (warp >> 2) * 64;
    const int wn = (warp & 3) * 32;
    const int lr = lane >> 2;
    const int lc = lane & 3;

    float c[4][4][4];
#pragma unroll
    for (int mf = 0; mf < 4; mf++)
#pragma unroll
        for (int nf = 0; nf < 4; nf++)
#pragma unroll
            for (int r = 0; r < 4; r++) c[mf][nf][r] = 0.f;

    const int KT = DMODEL / 32;      // 32 iterations
    gemm_issue<MODE>(sm, 0, bm, bn, 0, t);
    gemm_issue<MODE>(sm, 1, bm, bn, 32, t);

    for (int i = 0; i < KT; i++) {
        if (i + 1 < KT) CP_WAIT1(); else CP_WAIT0();
        __syncthreads();
        const float* As = sm + (i & 1) * GSTAGE;
        const float* Bs = As + GTILE;

#pragma unroll
        for (int kk = 0; kk < 32; kk += 8) {
            uint32_t a[4][4], b[4][2];
#pragma unroll
            for (int mf = 0; mf < 4; mf++) {
                int m0 = wm + mf * 16 + lr;
                a[mf][0] = fu(As[(m0    ) * 36 + kk + lc    ]);
                a[mf][1] = fu(As[(m0 + 8) * 36 + kk + lc    ]);
                a[mf][2] = fu(As[(m0    ) * 36 + kk + lc + 4]);
                a[mf][3] = fu(As[(m0 + 8) * 36 + kk + lc + 4]);
            }
#pragma unroll
            for (int nf = 0; nf < 4; nf++) {
                int n0 = wn + nf * 8 + lr;
                b[nf][0] = fu(Bs[n0 * 36 + kk + lc    ]);
                b[nf][1] = fu(Bs[n0 * 36 + kk + lc + 4]);
            }
#pragma unroll
            for (int mf = 0; mf < 4; mf++)
#pragma unroll
                for (int nf = 0; nf < 4; nf++)
                    mma8(c[mf][nf], a[mf][0], a[mf][1], a[mf][2], a[mf][3],
                         b[nf][0], b[nf][1]);
        }
        __syncthreads();
        if (i + 2 < KT) gemm_issue<MODE>(sm, i & 1, bm, bn, (i + 2) * 32, t);
    }

#pragma unroll
    for (int mf = 0; mf < 4; mf++) {
#pragma unroll
        for (int nf = 0; nf < 4; nf++) {
            int n = bn + wn + nf * 8 + 2 * lc;
            float b0 = bias[n], b1 = bias[n + 1];
#pragma unroll
            for (int rh = 0; rh < 2; rh++) {
                int m = bm + wm + mf * 16 + lr + rh * 8;
                float2 v;
                v.x = c[mf][nf][rh * 2 + 0] + b0;
                v.y = c[mf][nf][rh * 2 + 1] + b1;
                if (MODE == 0) {
                    v.x = tf32f(v.x);
                    v.y = tf32f(v.y);
                    int sel = n >> 10;
                    int nn  = n & 1023;
                    float* dst = (sel == 0) ? g_Q : (sel == 1) ? g_K : g_V;
                    *(float2*)&dst[((size_t)(nn >> 6) * SEQ + m) * HS + (nn & 63)] = v;
                } else {
                    *(float2*)&C[(size_t)m * DMODEL + n] = v;
                }
            }
        }
    }
}

// ---------------------------------------------------------------------------
// tf32 flash attention, cp.async 2-stage KV pipeline.
// Grid (S/128, NH), 256 threads (8 warps). Warp w owns q-rows [w*16, w*16+16).
// 64x64 KV tiles. Per-warp causal bound avoids fully-masked warps (NaN-safe).
// ---------------------------------------------------------------------------
#define BQ   128
#define KSTR 68   // == 4 mod 32: conflict-free for A/B frag pattern
#define VSTR 72   // == 8 mod 32: conflict-free for V B-frag pattern
#define KVSTAGE (64 * KSTR + 64 * VSTR)   // 8960 floats
// layout: Qs[128*68] | Ps[128*68] | stage0 {K,V} | stage1 {K,V}
#define ATTN_SMEM ((BQ * KSTR + BQ * KSTR + 2 * KVSTAGE) * 4)

__device__ __forceinline__ void kv_issue(float* kvs, int s, const float* kbase,
                                         const float* vbase, int jt, int t)
{
    float* Ks = kvs + s * KVSTAGE;
    float* Vs = Ks + 64 * KSTR;
    const float* kg = kbase + (size_t)jt * 64 * HS;
    const float* vg = vbase + (size_t)jt * 64 * HS;
#pragma unroll
    for (int j = 0; j < 4; j++) {
        int idx = t + j * 256;
        int row = idx >> 4;
        int col = (idx & 15) * 4;
        cp16(s2u(Ks + row * KSTR + col), kg + row * HS + col);
        cp16(s2u(Vs + row * VSTR + col), vg + row * HS + col);
    }
    CP_COMMIT();
}

__global__ __launch_bounds__(256) void attn_tc(const int* __restrict__ cmask)
{
    extern __shared__ float sm[];
    float* Qs  = sm;                   // [128][KSTR]
    float* Ps  = Qs + BQ * KSTR;       // [128][KSTR]
    float* kvs = Ps + BQ * KSTR;       // 2 stages of {K,V}

    const int h   = blockIdx.y;
    const int it  = gridDim.x - 1 - blockIdx.x;   // big tiles first
    const int qi0 = it * BQ;
    const int t    = threadIdx.x;
    const int warp = t >> 5;
    const int lane = t & 31;
    const int lr = lane >> 2;
    const int lc = lane & 3;
    const int w16 = warp * 16;
    const int causal = cmask ? cmask[0] : 1;

    const float* kbase = g_K + (size_t)h * SEQ * HS;
    const float* vbase = g_V + (size_t)h * SEQ * HS;

    const int jt_end_blk = causal ? 2 * it + 1 : (SEQ / 64 - 1);
    const int jt_end_w   = causal ? 2 * it + (warp >> 2) : (SEQ / 64 - 1);

    kv_issue(kvs, 0, kbase, vbase, 0, t);

    // Q tile: raw copy (already tf32)
    {
        const float* src = g_Q + ((size_t)h * SEQ + qi0) * HS;
#pragma unroll
        for (int j = 0; j < 8; j++) {
            int idx = t + j * 256;
            int row = idx >> 4;
            int col = (idx & 15) * 4;
            *(float4*)(Qs + row * KSTR + col) = ((const float4*)src)[idx];
        }
    }

    float mrow0 = -INFINITY, mrow1 = -INFINITY, l0 = 0.f, l1 = 0.f;
    float O[8][4];
#pragma unroll
    for (int nf = 0; nf < 8; nf++)
#pragma unroll
        for (int r = 0; r < 4; r++) O[nf][r] = 0.f;

    for (int jt = 0; jt <= jt_end_blk; jt++) {
        __syncthreads();                // all warps done with buf[(jt+1)&1]
        if (jt < jt_end_blk) {
            kv_issue(kvs, (jt + 1) & 1, kbase, vbase, jt + 1, t);
            CP_WAIT1();
        } else {
            CP_WAIT0();
        }
        __syncthreads();                // stage jt&1 visible to all warps

        const float* Ks = kvs + (jt & 1) * KVSTAGE;
        const float* Vs = Ks + 64 * KSTR;

        if (jt <= jt_end_w) {
            // ---- S = Q K^T (16x64 per warp) ----
            float c[8][4];
#pragma unroll
            for (int nf = 0; nf < 8; nf++)
#pragma unroll
                for (int r = 0; r < 4; r++) c[nf][r] = 0.f;

#pragma unroll
            for (int kk = 0; kk < HS; kk += 8) {
                uint32_t a0 = fu(Qs[(w16 + lr    ) * KSTR + kk + lc    ]);
                uint32_t a1 = fu(Qs[(w16 + lr + 8) * KSTR + kk + lc    ]);
                uint32_t a2 = fu(Qs[(w16 + lr    ) * KSTR + kk + lc + 4]);
                uint32_t a3 = fu(Qs[(w16 + lr + 8) * KSTR + kk + lc + 4]);
#pragma unroll
                for (int nf = 0; nf < 8; nf++) {
                    uint32_t b0 = fu(Ks[(nf * 8 + lr) * KSTR + kk + lc    ]);
                    uint32_t b1 = fu(Ks[(nf * 8 + lr) * KSTR + kk + lc + 4]);
                    mma8(c[nf], a0, a1, a2, a3, b0, b1);
                }
            }

            // ---- mask + scale ----
            const int row0 = qi0 + w16 + lr;
            const int row1 = row0 + 8;
            const bool diag = causal && (jt * 64 + 63 > qi0 + w16);
#pragma unroll
            for (int nf = 0; nf < 8; nf++) {
                int col = jt * 64 + nf * 8 + 2 * lc;
                c[nf][0] *= 0.125f; c[nf][1] *= 0.125f;
                c[nf][2] *= 0.125f; c[nf][3] *= 0.125f;
                if (diag) {
                    if (col     > row0) c[nf][0] = -INFINITY;
                    if (col + 1 > row0) c[nf][1] = -INFINITY;
                    if (col     > row1) c[nf][2] = -INFINITY;
                    if (col + 1 > row1) c[nf][3] = -INFINITY;
                }
            }

            // ---- online softmax (rows live in lane quads) ----
            float mx0 = -INFINITY, mx1 = -INFINITY;
#pragma unroll
            for (int nf = 0; nf < 8; nf++) {
                mx0 = fmaxf(mx0, fmaxf(c[nf][0], c[nf][1]));
                mx1 = fmaxf(mx1, fmaxf(c[nf][2], c[nf][3]));
            }
            mx0 = fmaxf(mx0, __shfl_xor_sync(0xffffffffu, mx0, 1));
            mx0 = fmaxf(mx0, __shfl_xor_sync(0xffffffffu, mx0, 2));
            mx1 = fmaxf(mx1, __shfl_xor_sync(0xffffffffu, mx1, 1));
            mx1 = fmaxf(mx1, __shfl_xor_sync(0xffffffffu, mx1, 2));

            const float mn0 = fmaxf(mrow0, mx0);
            const float mn1 = fmaxf(mrow1, mx1);
            const float al0 = __expf(mrow0 - mn0);
            const float al1 = __expf(mrow1 - mn1);
            float s0 = 0.f, s1 = 0.f;
#pragma unroll
            for (int nf = 0; nf < 8; nf++) {
                c[nf][0] = __expf(c[nf][0] - mn0); s0 += c[nf][0];
                c[nf][1] = __expf(c[nf][1] - mn0); s0 += c[nf][1];
                c[nf][2] = __expf(c[nf][2] - mn1); s1 += c[nf][2];
                c[nf][3] = __expf(c[nf][3] - mn1); s1 += c[nf][3];
            }
            s0 += __shfl_xor_sync(0xffffffffu, s0, 1);
            s0 += __shfl_xor_sync(0xffffffffu, s0, 2);
            s1 += __shfl_xor_sync(0xffffffffu, s1, 1);
            s1 += __shfl_xor_sync(0xffffffffu, s1, 2);
            l0 = l0 * al0 + s0;  l1 = l1 * al1 + s1;
            mrow0 = mn0;         mrow1 = mn1;
#pragma unroll
            for (int nf = 0; nf < 8; nf++) {
                O[nf][0] *= al0; O[nf][1] *= al0;
                O[nf][2] *= al1; O[nf][3] *= al1;
            }

            // ---- P -> smem (tf32), warp-private region ----
#pragma unroll
            for (int nf = 0; nf < 8; nf++) {
                float2 p0, p1;
                p0.x = tf32f(c[nf][0]); p0.y = tf32f(c[nf][1]);
                p1.x = tf32f(c[nf][2]); p1.y = tf32f(c[nf][3]);
                *(float2*)&Ps[(w16 + lr    ) * KSTR + nf * 8 + 2 * lc] = p0;
                *(float2*)&Ps[(w16 + lr + 8) * KSTR + nf * 8 + 2 * lc] = p1;
            }
            __syncwarp();

            // ---- O += P V ----
#pragma unroll
            for (int kk = 0; kk < 64; kk += 8) {
                uint32_t a0 = fu(Ps[(w16 + lr    ) * KSTR + kk + lc    ]);
                uint32_t a1 = fu(Ps[(w16 + lr + 8) * KSTR + kk + lc    ]);
                uint32_t a2 = fu(Ps[(w16 + lr    ) * KSTR + kk + lc + 4]);
                uint32_t a3 = fu(Ps[(w16 + lr + 8) * KSTR + kk + lc + 4]);
#pragma unroll
                for (int nf = 0; nf < 8; nf++) {
                    uint32_t b0 = fu(Vs[(kk + lc    ) * VSTR + nf * 8 + lr]);
                    uint32_t b1 = fu(Vs[(kk + lc + 4) * VSTR + nf * 8 + lr]);
                    mma8(O[nf], a0, a1, a2, a3, b0, b1);
                }
            }
        }
    }

    // ---- epilogue: normalize, round to tf32 (gemm1 input), store ----
    const float inv0 = 1.f / l0;
    const float inv1 = 1.f / l1;
#pragma unroll
    for (int nf = 0; nf < 8; nf++) {
        int col = h * HS + nf * 8 + 2 * lc;
        float2 v0, v1;
        v0.x = tf32f(O[nf][0] * inv0); v0.y = tf32f(O[nf][1] * inv0);
        v1.x = tf32f(O[nf][2] * inv1); v1.y = tf32f(O[nf][3] * inv1);
        *(float2*)&g_attn[(size_t)(qi0 + w16 + lr    ) * DMODEL + col] = v0;
        *(float2*)&g_attn[(size_t)(qi0 + w16 + lr + 8) * DMODEL + col] = v1;
    }
}

// ---------------------------------------------------------------------------
extern "C" void kernel_launch(void* const* d_in, const int* in_sizes, int n_in,
                              void* d_out, int out_size)
{
    const float* x     = (const float*)d_in[0];
    const float* w_qkv = (const float*)d_in[1];
    const float* b_qkv = (const float*)d_in[2];
    const float* w_o   = (const float*)d_in[3];
    const float* b_o   = (const float*)d_in[4];
    const int*   cmask = (n_in > 5) ? (const int*)d_in[5] : nullptr;

    cudaFuncSetAttribute(gemm_tc<0>,
                         cudaFuncAttributeMaxDynamicSharedMemorySize, GEMM_SMEM);
    cudaFuncSetAttribute(gemm_tc<1>,
                         cudaFuncAttributeMaxDynamicSharedMemorySize, GEMM_SMEM);
    cudaFuncSetAttribute(attn_tc,
                         cudaFuncAttributeMaxDynamicSharedMemorySize, ATTN_SMEM);

    prepass<<<2048, 512>>>(x, w_qkv, w_o);
    gemm_tc<0><<<dim3(3072 / 128, SEQ / 128), 256, GEMM_SMEM>>>(b_qkv, nullptr);
    attn_tc<<<dim3(SEQ / BQ, NH), 256, ATTN_SMEM>>>(cmask);
    gemm_tc<1><<<dim3(DMODEL / 128, SEQ / 128), 256, GEMM_SMEM>>>(b_o,
                                                                  (float*)d_out);
}

// round 6
// speedup vs baseline: 1.0855x; 1.0855x over previous
#include <cuda_runtime.h>
#include <math.h>
#include <stdint.h>

#define SEQ    4096
#define DMODEL 1024
#define NH     16
#define HS     64

// Scratch (no cudaMalloc allowed). Q/K/V hold tf32-rounded bit patterns
// (rounded in gemm0 epilogue); g_attn holds raw fp32 (gemm1 rounds on load).
__device__ float g_Q[NH * SEQ * HS];
__device__ float g_K[NH * SEQ * HS];
__device__ float g_V[NH * SEQ * HS];
__device__ float g_attn[SEQ * DMODEL];

__device__ __forceinline__ uint32_t f2tf32(float x) {
    uint32_t r;
    asm("cvt.rna.tf32.f32 %0, %1;" : "=r"(r) : "f"(x));
    return r;
}
__device__ __forceinline__ float tf32f(float x) { return __uint_as_float(f2tf32(x)); }
__device__ __forceinline__ uint32_t fu(float x) { return __float_as_uint(x); }

__device__ __forceinline__ void mma8(float* c,
    uint32_t a0, uint32_t a1, uint32_t a2, uint32_t a3,
    uint32_t b0, uint32_t b1)
{
    asm volatile(
        "mma.sync.aligned.m16n8k8.row.col.f32.tf32.tf32.f32 "
        "{%0,%1,%2,%3},{%4,%5,%6,%7},{%8,%9},{%0,%1,%2,%3};"
        : "+f"(c[0]), "+f"(c[1]), "+f"(c[2]), "+f"(c[3])
        : "r"(a0), "r"(a1), "r"(a2), "r"(a3), "r"(b0), "r"(b1));
}

// ---------------------------------------------------------------------------
// tf32 tensor-core GEMM (exact R2 version — known-good 193/55us).
// C[M,N] = A[M,1024] * B[N,1024]^T + bias[N]
// MODE 0: A = x, scatter tf32-rounded into g_Q/g_K/g_V (N = 3072)
// MODE 1: A = g_attn, write fp32 C = d_out (N = 1024)
// ---------------------------------------------------------------------------
template <int MODE>
__global__ __launch_bounds__(256) void gemm_tc(
    const float* __restrict__ A, const float* __restrict__ B,
    const float* __restrict__ bias, float* __restrict__ C)
{
    __shared__ float As[128 * 36];
    __shared__ float Bs[128 * 36];

    const float* __restrict__ Ap = (MODE == 0) ? A : g_attn;
    const int bm = blockIdx.y * 128;
    const int bn = blockIdx.x * 128;
    const int t    = threadIdx.x;
    const int warp = t >> 5;
    const int lane = t & 31;
    const int wm = (warp >> 2) * 64;
    const int wn = (warp & 3) * 32;
    const int lr = lane >> 2;
    const int lc = lane & 3;

    float c[4][4][4];
#pragma unroll
    for (int mf = 0; mf < 4; mf++)
#pragma unroll
        for (int nf = 0; nf < 4; nf++)
#pragma unroll
            for (int r = 0; r < 4; r++) c[mf][nf][r] = 0.f;

    for (int k0 = 0; k0 < DMODEL; k0 += 32) {
        __syncthreads();
#pragma unroll
        for (int j = 0; j < 4; j++) {
            int idx = t + j * 256;
            int row = idx >> 3;
            int col = (idx & 7) * 4;
            float4 va = *(const float4*)(Ap + (size_t)(bm + row) * DMODEL + k0 + col);
            float4 vb = *(const float4*)(B  + (size_t)(bn + row) * DMODEL + k0 + col);
            float4 wa, wb;
            wa.x = tf32f(va.x); wa.y = tf32f(va.y); wa.z = tf32f(va.z); wa.w = tf32f(va.w);
            wb.x = tf32f(vb.x); wb.y = tf32f(vb.y); wb.z = tf32f(vb.z); wb.w = tf32f(vb.w);
            *(float4*)(As + row * 36 + col) = wa;
            *(float4*)(Bs + row * 36 + col) = wb;
        }
        __syncthreads();

#pragma unroll
        for (int kk = 0; kk < 32; kk += 8) {
            uint32_t a[4][4], b[4][2];
#pragma unroll
            for (int mf = 0; mf < 4; mf++) {
                int m0 = wm + mf * 16 + lr;
                a[mf][0] = fu(As[(m0    ) * 36 + kk + lc    ]);
                a[mf][1] = fu(As[(m0 + 8) * 36 + kk + lc    ]);
                a[mf][2] = fu(As[(m0    ) * 36 + kk + lc + 4]);
                a[mf][3] = fu(As[(m0 + 8) * 36 + kk + lc + 4]);
            }
#pragma unroll
            for (int nf = 0; nf < 4; nf++) {
                int n0 = wn + nf * 8 + lr;
                b[nf][0] = fu(Bs[n0 * 36 + kk + lc    ]);
                b[nf][1] = fu(Bs[n0 * 36 + kk + lc + 4]);
            }
#pragma unroll
            for (int mf = 0; mf < 4; mf++)
#pragma unroll
                for (int nf = 0; nf < 4; nf++)
                    mma8(c[mf][nf], a[mf][0], a[mf][1], a[mf][2], a[mf][3],
                         b[nf][0], b[nf][1]);
        }
    }

#pragma unroll
    for (int mf = 0; mf < 4; mf++) {
#pragma unroll
        for (int nf = 0; nf < 4; nf++) {
            int n = bn + wn + nf * 8 + 2 * lc;
            float b0 = bias[n], b1 = bias[n + 1];
#pragma unroll
            for (int rh = 0; rh < 2; rh++) {
                int m = bm + wm + mf * 16 + lr + rh * 8;
                float2 v;
                v.x = c[mf][nf][rh * 2 + 0] + b0;
                v.y = c[mf][nf][rh * 2 + 1] + b1;
                if (MODE == 0) {
                    v.x = tf32f(v.x);      // pre-round: attention loads are raw
                    v.y = tf32f(v.y);
                    int sel = n >> 10;
                    int nn  = n & 1023;
                    float* dst = (sel == 0) ? g_Q : (sel == 1) ? g_K : g_V;
                    *(float2*)&dst[((size_t)(nn >> 6) * SEQ + m) * HS + (nn & 63)] = v;
                } else {
                    *(float2*)&C[(size_t)m * DMODEL + n] = v;
                }
            }
        }
    }
}

// ---------------------------------------------------------------------------
// tf32 flash attention, R2 structure + P-aliases-K smem compaction.
// Grid (S/64, NH), 128 threads (4 warps). Warp w owns q-rows [w*16, w*16+16).
// smem = Qs(64x68) + Ks/Ps shared(64x68) + Vs(64x72) = 53 KB -> 4 CTAs/SM
// (16 warps, vs 12 in R2). One extra __syncthreads after QK makes the
// aliasing safe: all warps finish reading Ks before P overwrites it, and
// each warp's PV reads only its own warp-private P rows.
// ---------------------------------------------------------------------------
#define QSTR 68   // == 4 mod 32: conflict-free for A/B frag pattern
#define VSTR 72   // == 8 mod 32: conflict-free for V B-frag pattern
#define ATTN_SMEM ((2 * 64 * QSTR + 64 * VSTR) * 4)   // 53248 B

__global__ __launch_bounds__(128) void attn_tc(const int* __restrict__ cmask)
{
    extern __shared__ float sm[];
    float* Qs = sm;                       // [64][QSTR]
    float* Ks = Qs + 64 * QSTR;           // [64][QSTR]  (P aliases this)
    float* Vs = Ks + 64 * QSTR;           // [64][VSTR]
    float* Ps = Ks;                       // alias!

    const int h   = blockIdx.y;
    const int it  = gridDim.x - 1 - blockIdx.x;   // big tiles first
    const int qi0 = it * 64;
    const int t    = threadIdx.x;
    const int warp = t >> 5;
    const int lane = t & 31;
    const int lr = lane >> 2;
    const int lc = lane & 3;
    const int w16 = warp * 16;
    const int causal = cmask ? cmask[0] : 1;

    // Q tile: raw copy (already tf32-rounded)
    {
        const float4* src = (const float4*)(g_Q + ((size_t)h * SEQ + qi0) * HS);
#pragma unroll
        for (int j = 0; j < 8; j++) {
            int idx = t + j * 128;
            int row = idx >> 4;
            int col = (idx & 15) * 4;
            *(float4*)(Qs + row * QSTR + col) = src[idx];
        }
    }

    float mrow0 = -INFINITY, mrow1 = -INFINITY, l0 = 0.f, l1 = 0.f;
    float O[8][4];
#pragma unroll
    for (int nf = 0; nf < 8; nf++)
#pragma unroll
        for (int r = 0; r < 4; r++) O[nf][r] = 0.f;

    const int jt_end = causal ? it : (SEQ / 64 - 1);
    for (int jt = 0; jt <= jt_end; jt++) {
        __syncthreads();                 // prev iter: PV done with Vs, P(Ks)
        {
            const float4* ksrc = (const float4*)(g_K + ((size_t)h * SEQ + jt * 64) * HS);
            const float4* vsrc = (const float4*)(g_V + ((size_t)h * SEQ + jt * 64) * HS);
#pragma unroll
            for (int j = 0; j < 8; j++) {
                int idx = t + j * 128;
                int row = idx >> 4;
                int col = (idx & 15) * 4;
                *(float4*)(Ks + row * QSTR + col) = ksrc[idx];
                *(float4*)(Vs + row * VSTR + col) = vsrc[idx];
            }
        }
        __syncthreads();

        // ---- S = Q K^T (16x64 per warp) ----
        float c[8][4];
#pragma unroll
        for (int nf = 0; nf < 8; nf++)
#pragma unroll
            for (int r = 0; r < 4; r++) c[nf][r] = 0.f;

#pragma unroll
        for (int kk = 0; kk < HS; kk += 8) {
            uint32_t a0 = fu(Qs[(w16 + lr    ) * QSTR + kk + lc    ]);
            uint32_t a1 = fu(Qs[(w16 + lr + 8) * QSTR + kk + lc    ]);
            uint32_t a2 = fu(Qs[(w16 + lr    ) * QSTR + kk + lc + 4]);
            uint32_t a3 = fu(Qs[(w16 + lr + 8) * QSTR + kk + lc + 4]);
#pragma unroll
            for (int nf = 0; nf < 8; nf++) {
                uint32_t b0 = fu(Ks[(nf * 8 + lr) * QSTR + kk + lc    ]);
                uint32_t b1 = fu(Ks[(nf * 8 + lr) * QSTR + kk + lc + 4]);
                mma8(c[nf], a0, a1, a2, a3, b0, b1);
            }
        }

        // ---- mask + scale ----
        const bool diag = causal && (jt == it);
        const int row0 = qi0 + w16 + lr;
        const int row1 = row0 + 8;
#pragma unroll
        for (int nf = 0; nf < 8; nf++) {
            int col = jt * 64 + nf * 8 + 2 * lc;
            c[nf][0] *= 0.125f; c[nf][1] *= 0.125f;
            c[nf][2] *= 0.125f; c[nf][3] *= 0.125f;
            if (diag) {
                if (col     > row0) c[nf][0] = -INFINITY;
                if (col + 1 > row0) c[nf][1] = -INFINITY;
                if (col     > row1) c[nf][2] = -INFINITY;
                if (col + 1 > row1) c[nf][3] = -INFINITY;
            }
        }

        // ---- online softmax (rows live in lane quads) ----
        float mx0 = -INFINITY, mx1 = -INFINITY;
#pragma unroll
        for (int nf = 0; nf < 8; nf++) {
            mx0 = fmaxf(mx0, fmaxf(c[nf][0], c[nf][1]));
            mx1 = fmaxf(mx1, fmaxf(c[nf][2], c[nf][3]));
        }
        mx0 = fmaxf(mx0, __shfl_xor_sync(0xffffffffu, mx0, 1));
        mx0 = fmaxf(mx0, __shfl_xor_sync(0xffffffffu, mx0, 2));
        mx1 = fmaxf(mx1, __shfl_xor_sync(0xffffffffu, mx1, 1));
        mx1 = fmaxf(mx1, __shfl_xor_sync(0xffffffffu, mx1, 2));

        const float mn0 = fmaxf(mrow0, mx0);
        const float mn1 = fmaxf(mrow1, mx1);
        const float al0 = __expf(mrow0 - mn0);
        const float al1 = __expf(mrow1 - mn1);
        float s0 = 0.f, s1 = 0.f;
#pragma unroll
        for (int nf = 0; nf < 8; nf++) {
            c[nf][0] = __expf(c[nf][0] - mn0); s0 += c[nf][0];
            c[nf][1] = __expf(c[nf][1] - mn0); s0 += c[nf][1];
            c[nf][2] = __expf(c[nf][2] - mn1); s1 += c[nf][2];
            c[nf][3] = __expf(c[nf][3] - mn1); s1 += c[nf][3];
        }
        s0 += __shfl_xor_sync(0xffffffffu, s0, 1);
        s0 += __shfl_xor_sync(0xffffffffu, s0, 2);
        s1 += __shfl_xor_sync(0xffffffffu, s1, 1);
        s1 += __shfl_xor_sync(0xffffffffu, s1, 2);
        l0 = l0 * al0 + s0;  l1 = l1 * al1 + s1;
        mrow0 = mn0;         mrow1 = mn1;
#pragma unroll
        for (int nf = 0; nf < 8; nf++) {
            O[nf][0] *= al0; O[nf][1] *= al0;
            O[nf][2] *= al1; O[nf][3] *= al1;
        }

        // ---- barrier: all warps done READING Ks; safe to overwrite with P ----
        __syncthreads();

        // ---- P -> smem (tf32), warp-private rows of the aliased buffer ----
#pragma unroll
        for (int nf = 0; nf < 8; nf++) {
            float2 p0, p1;
            p0.x = tf32f(c[nf][0]); p0.y = tf32f(c[nf][1]);
            p1.x = tf32f(c[nf][2]); p1.y = tf32f(c[nf][3]);
            *(float2*)&Ps[(w16 + lr    ) * QSTR + nf * 8 + 2 * lc] = p0;
            *(float2*)&Ps[(w16 + lr + 8) * QSTR + nf * 8 + 2 * lc] = p1;
        }
        __syncwarp();

        // ---- O += P V (reads only own-warp P rows + all Vs) ----
#pragma unroll
        for (int kk = 0; kk < 64; kk += 8) {
            uint32_t a0 = fu(Ps[(w16 + lr    ) * QSTR + kk + lc    ]);
            uint32_t a1 = fu(Ps[(w16 + lr + 8) * QSTR + kk + lc    ]);
            uint32_t a2 = fu(Ps[(w16 + lr    ) * QSTR + kk + lc + 4]);
            uint32_t a3 = fu(Ps[(w16 + lr + 8) * QSTR + kk + lc + 4]);
#pragma unroll
            for (int nf = 0; nf < 8; nf++) {
                uint32_t b0 = fu(Vs[(kk + lc    ) * VSTR + nf * 8 + lr]);
                uint32_t b1 = fu(Vs[(kk + lc + 4) * VSTR + nf * 8 + lr]);
                mma8(O[nf], a0, a1, a2, a3, b0, b1);
            }
        }
    }

    // ---- epilogue: normalize, write raw fp32 (gemm1 rounds on load) ----
    const float inv0 = 1.f / l0;
    const float inv1 = 1.f / l1;
#pragma unroll
    for (int nf = 0; nf < 8; nf++) {
        int col = h * HS + nf * 8 + 2 * lc;
        float2 v0, v1;
        v0.x = O[nf][0] * inv0; v0.y = O[nf][1] * inv0;
        v1.x = O[nf][2] * inv1; v1.y = O[nf][3] * inv1;
        *(float2*)&g_attn[(size_t)(qi0 + w16 + lr    ) * DMODEL + col] = v0;
        *(float2*)&g_attn[(size_t)(qi0 + w16 + lr + 8) * DMODEL + col] = v1;
    }
}

// ---------------------------------------------------------------------------
extern "C" void kernel_launch(void* const* d_in, const int* in_sizes, int n_in,
                              void* d_out, int out_size)
{
    const float* x     = (const float*)d_in[0];
    const float* w_qkv = (const float*)d_in[1];
    const float* b_qkv = (const float*)d_in[2];
    const float* w_o   = (const float*)d_in[3];
    const float* b_o   = (const float*)d_in[4];
    const int*   cmask = (n_in > 5) ? (const int*)d_in[5] : nullptr;

    cudaFuncSetAttribute(attn_tc,
                         cudaFuncAttributeMaxDynamicSharedMemorySize, ATTN_SMEM);

    gemm_tc<0><<<dim3(3072 / 128, SEQ / 128), 256>>>(x, w_qkv, b_qkv, nullptr);
    attn_tc<<<dim3(SEQ / 64, NH), 128, ATTN_SMEM>>>(cmask);
    gemm_tc<1><<<dim3(DMODEL / 128, SEQ / 128), 256>>>(nullptr, w_o, b_o,
                                                       (float*)d_out);
}

// round 7
// speedup vs baseline: 1.6609x; 1.5300x over previous
#include <cuda_runtime.h>
#include <cuda_fp16.h>
#include <math.h>
#include <stdint.h>

#define SEQ    4096
#define DMODEL 1024
#define NH     16
#define HS     64

// Scratch (no cudaMalloc). Q/K: [h][tok][d] fp16. Vt: [h][d][tok] fp16
// (transposed so PV mma B-fragments are half2 pairs along token).
// g_attn: [tok][1024] fp16 (consumed raw by gemm1).
__device__ __half g_Q[NH * SEQ * HS];
__device__ __half g_K[NH * SEQ * HS];
__device__ __half g_Vt[NH * HS * SEQ];
__device__ __half g_attn[SEQ * DMODEL];

__device__ __forceinline__ uint32_t packh2(float x, float y) {
    __half2 h = __float22half2_rn(make_float2(x, y));
    return *(uint32_t*)&h;
}

__device__ __forceinline__ void mma16(float* c,
    uint32_t a0, uint32_t a1, uint32_t a2, uint32_t a3,
    uint32_t b0, uint32_t b1)
{
    asm volatile(
        "mma.sync.aligned.m16n8k16.row.col.f32.f16.f16.f32 "
        "{%0,%1,%2,%3},{%4,%5,%6,%7},{%8,%9},{%0,%1,%2,%3};"
        : "+f"(c[0]), "+f"(c[1]), "+f"(c[2]), "+f"(c[3])
        : "r"(a0), "r"(a1), "r"(a2), "r"(a3), "r"(b0), "r"(b1));
}

// ---------------------------------------------------------------------------
// fp16 tensor-core GEMM: C[M,N] = A[M,1024] * B[N,1024]^T + bias[N]
// MODE 0: A = x (fp32->h), B = w_qkv (fp32->h), scatter to g_Q/g_K/g_Vt
// MODE 1: A = g_attn (fp16 raw), B = w_o (fp32->h), write fp32 C = d_out
// 128x128 block, BK=32, 256 threads (8 warps), warp tile 64x32, m16n8k16.
// Smem in half2 units, row stride 20 (40 halves = 32 + 8 pad):
// fragment LDS pattern (lr*20 + lc [+4]) mod 32 hits 32 distinct banks.
// ---------------------------------------------------------------------------
template <int MODE>
__global__ __launch_bounds__(256) void gemm_h(
    const float* __restrict__ A, const float* __restrict__ B,
    const float* __restrict__ bias, float* __restrict__ C)
{
    __shared__ uint32_t As2[128 * 20];   // half2 units
    __shared__ uint32_t Bs2[128 * 20];

    const int bm = blockIdx.y * 128;
    const int bn = blockIdx.x * 128;
    const int t    = threadIdx.x;
    const int warp = t >> 5;
    const int lane = t & 31;
    const int wm = (warp >> 2) * 64;
    const int wn = (warp & 3) * 32;
    const int lr = lane >> 2;
    const int lc = lane & 3;

    float c[4][4][4];
#pragma unroll
    for (int mf = 0; mf < 4; mf++)
#pragma unroll
        for (int nf = 0; nf < 4; nf++)
#pragma unroll
            for (int r = 0; r < 4; r++) c[mf][nf][r] = 0.f;

    for (int k0 = 0; k0 < DMODEL; k0 += 32) {
        __syncthreads();
#pragma unroll
        for (int j = 0; j < 4; j++) {
            int idx = t + j * 256;          // 1024 quads per operand tile
            int row = idx >> 3;
            int col = (idx & 7) * 4;        // element col (0..28)
            uint2 ha;
            if (MODE == 0) {
                float4 va = *(const float4*)(A + (size_t)(bm + row) * DMODEL + k0 + col);
                ha.x = packh2(va.x, va.y);
                ha.y = packh2(va.z, va.w);
            } else {
                ha = *(const uint2*)(g_attn + (size_t)(bm + row) * DMODEL + k0 + col);
            }
            *(uint2*)&As2[row * 20 + col / 2] = ha;

            float4 vb = *(const float4*)(B + (size_t)(bn + row) * DMODEL + k0 + col);
            uint2 hb;
            hb.x = packh2(vb.x, vb.y);
            hb.y = packh2(vb.z, vb.w);
            *(uint2*)&Bs2[row * 20 + col / 2] = hb;
        }
        __syncthreads();

#pragma unroll
        for (int kk2 = 0; kk2 < 16; kk2 += 8) {     // two k16 steps per BK=32
            uint32_t a[4][4], b[4][2];
#pragma unroll
            for (int mf = 0; mf < 4; mf++) {
                int m0 = wm + mf * 16 + lr;
                a[mf][0] = As2[(m0    ) * 20 + kk2 + lc    ];
                a[mf][1] = As2[(m0 + 8) * 20 + kk2 + lc    ];
                a[mf][2] = As2[(m0    ) * 20 + kk2 + lc + 4];
                a[mf][3] = As2[(m0 + 8) * 20 + kk2 + lc + 4];
            }
#pragma unroll
            for (int nf = 0; nf < 4; nf++) {
                int n0 = wn + nf * 8 + lr;
                b[nf][0] = Bs2[n0 * 20 + kk2 + lc    ];
                b[nf][1] = Bs2[n0 * 20 + kk2 + lc + 4];
            }
#pragma unroll
            for (int mf = 0; mf < 4; mf++)
#pragma unroll
                for (int nf = 0; nf < 4; nf++)
                    mma16(c[mf][nf], a[mf][0], a[mf][1], a[mf][2], a[mf][3],
                          b[nf][0], b[nf][1]);
        }
    }

#pragma unroll
    for (int mf = 0; mf < 4; mf++) {
#pragma unroll
        for (int nf = 0; nf < 4; nf++) {
            int n = bn + wn + nf * 8 + 2 * lc;
            float b0 = bias[n], b1 = bias[n + 1];
#pragma unroll
            for (int rh = 0; rh < 2; rh++) {
                int m = bm + wm + mf * 16 + lr + rh * 8;
                float vx = c[mf][nf][rh * 2 + 0] + b0;
                float vy = c[mf][nf][rh * 2 + 1] + b1;
                if (MODE == 0) {
                    int sel = n >> 10;
                    int nn  = n & 1023;
                    int hd  = nn >> 6;
                    int d   = nn & 63;
                    if (sel < 2) {
                        __half* dst = (sel == 0) ? g_Q : g_K;
                        uint32_t h = packh2(vx, vy);
                        *(uint32_t*)&dst[((size_t)hd * SEQ + m) * HS + d] = h;
                    } else {
                        g_Vt[((size_t)hd * HS + d    ) * SEQ + m] = __float2half_rn(vx);
                        g_Vt[((size_t)hd * HS + d + 1) * SEQ + m] = __float2half_rn(vy);
                    }
                } else {
                    float2 v; v.x = vx; v.y = vy;
                    *(float2*)&C[(size_t)m * DMODEL + n] = v;
                }
            }
        }
    }
}

// ---------------------------------------------------------------------------
// fp16 flash attention. Grid (S/64, NH), 128 threads (4 warps).
// Warp w owns q-rows [w*16, w*16+16). m16n8k16 fragments from half2 smem,
// row stride 36 half2 (72 halves): (lr*36 + lc) mod 32 = lr*4 + lc -> 32
// distinct banks. P aliases Ks (extra barrier after QK, as in R6).
// ---------------------------------------------------------------------------
#define ASTR2 36   // half2 stride per 64-wide row (64 + 8 pad halves)

__global__ __launch_bounds__(128) void attn_h(const int* __restrict__ cmask)
{
    __shared__ uint32_t Qs2[64 * ASTR2];
    __shared__ uint32_t Ks2[64 * ASTR2];   // P aliases this
    __shared__ uint32_t Vs2[64 * ASTR2];   // holds Vt tile: [d][token]
    uint32_t* Ps2 = Ks2;

    const int h   = blockIdx.y;
    const int it  = gridDim.x - 1 - blockIdx.x;   // big tiles first
    const int qi0 = it * 64;
    const int t    = threadIdx.x;
    const int warp = t >> 5;
    const int lane = t & 31;
    const int lr = lane >> 2;
    const int lc = lane & 3;
    const int w16 = warp * 16;
    const int causal = cmask ? cmask[0] : 1;

    // Q tile: 64 rows x 64 halves; uint4 = 8 halves
    {
        const __half* src = g_Q + ((size_t)h * SEQ + qi0) * HS;
#pragma unroll
        for (int j = 0; j < 4; j++) {
            int idx = t + j * 128;          // 512 uint4
            int row = idx >> 3;
            int col = (idx & 7) * 8;        // halves
            *(uint4*)&Qs2[row * ASTR2 + col / 2] =
                *(const uint4*)(src + (size_t)row * HS + col);
        }
    }

    float mrow0 = -INFINITY, mrow1 = -INFINITY, l0 = 0.f, l1 = 0.f;
    float O[8][4];
#pragma unroll
    for (int nf = 0; nf < 8; nf++)
#pragma unroll
        for (int r = 0; r < 4; r++) O[nf][r] = 0.f;

    const int jt_end = causal ? it : (SEQ / 64 - 1);
    for (int jt = 0; jt <= jt_end; jt++) {
        __syncthreads();                 // prev iter done with Vs & P(Ks)
        {
            const __half* ksrc = g_K + ((size_t)h * SEQ + jt * 64) * HS;
            const __half* vsrc = g_Vt + (size_t)h * HS * SEQ + jt * 64;
#pragma unroll
            for (int j = 0; j < 4; j++) {
                int idx = t + j * 128;
                int row = idx >> 3;
                int col = (idx & 7) * 8;
                *(uint4*)&Ks2[row * ASTR2 + col / 2] =
                    *(const uint4*)(ksrc + (size_t)row * HS + col);
                // Vt tile: row = d, cols = tokens jt*64 + col
                *(uint4*)&Vs2[row * ASTR2 + col / 2] =
                    *(const uint4*)(vsrc + (size_t)row * SEQ + col);
            }
        }
        __syncthreads();

        // ---- S = Q K^T (16x64 per warp), 4 k16 steps ----
        float c[8][4];
#pragma unroll
        for (int nf = 0; nf < 8; nf++)
#pragma unroll
            for (int r = 0; r < 4; r++) c[nf][r] = 0.f;

#pragma unroll
        for (int kk2 = 0; kk2 < 32; kk2 += 8) {
            uint32_t a0 = Qs2[(w16 + lr    ) * ASTR2 + kk2 + lc    ];
            uint32_t a1 = Qs2[(w16 + lr + 8) * ASTR2 + kk2 + lc    ];
            uint32_t a2 = Qs2[(w16 + lr    ) * ASTR2 + kk2 + lc + 4];
            uint32_t a3 = Qs2[(w16 + lr + 8) * ASTR2 + kk2 + lc + 4];
#pragma unroll
            for (int nf = 0; nf < 8; nf++) {
                uint32_t b0 = Ks2[(nf * 8 + lr) * ASTR2 + kk2 + lc    ];
                uint32_t b1 = Ks2[(nf * 8 + lr) * ASTR2 + kk2 + lc + 4];
                mma16(c[nf], a0, a1, a2, a3, b0, b1);
            }
        }

        // ---- mask + scale ----
        const bool diag = causal && (jt == it);
        const int row0 = qi0 + w16 + lr;
        const int row1 = row0 + 8;
#pragma unroll
        for (int nf = 0; nf < 8; nf++) {
            int col = jt * 64 + nf * 8 + 2 * lc;
            c[nf][0] *= 0.125f; c[nf][1] *= 0.125f;
            c[nf][2] *= 0.125f; c[nf][3] *= 0.125f;
            if (diag) {
                if (col     > row0) c[nf][0] = -INFINITY;
                if (col + 1 > row0) c[nf][1] = -INFINITY;
                if (col     > row1) c[nf][2] = -INFINITY;
                if (col + 1 > row1) c[nf][3] = -INFINITY;
            }
        }

        // ---- online softmax (rows live in lane quads) ----
        float mx0 = -INFINITY, mx1 = -INFINITY;
#pragma unroll
        for (int nf = 0; nf < 8; nf++) {
            mx0 = fmaxf(mx0, fmaxf(c[nf][0], c[nf][1]));
            mx1 = fmaxf(mx1, fmaxf(c[nf][2], c[nf][3]));
        }
        mx0 = fmaxf(mx0, __shfl_xor_sync(0xffffffffu, mx0, 1));
        mx0 = fmaxf(mx0, __shfl_xor_sync(0xffffffffu, mx0, 2));
        mx1 = fmaxf(mx1, __shfl_xor_sync(0xffffffffu, mx1, 1));
        mx1 = fmaxf(mx1, __shfl_xor_sync(0xffffffffu, mx1, 2));

        const float mn0 = fmaxf(mrow0, mx0);
        const float mn1 = fmaxf(mrow1, mx1);
        const float al0 = __expf(mrow0 - mn0);
        const float al1 = __expf(mrow1 - mn1);
        float s0 = 0.f, s1 = 0.f;
#pragma unroll
        for (int nf = 0; nf < 8; nf++) {
            c[nf][0] = __expf(c[nf][0] - mn0); s0 += c[nf][0];
            c[nf][1] = __expf(c[nf][1] - mn0); s0 += c[nf][1];
            c[nf][2] = __expf(c[nf][2] - mn1); s1 += c[nf][2];
            c[nf][3] = __expf(c[nf][3] - mn1); s1 += c[nf][3];
        }
        s0 += __shfl_xor_sync(0xffffffffu, s0, 1);
        s0 += __shfl_xor_sync(0xffffffffu, s0, 2);
        s1 += __shfl_xor_sync(0xffffffffu, s1, 1);
        s1 += __shfl_xor_sync(0xffffffffu, s1, 2);
        l0 = l0 * al0 + s0;  l1 = l1 * al1 + s1;
        mrow0 = mn0;         mrow1 = mn1;
#pragma unroll
        for (int nf = 0; nf < 8; nf++) {
            O[nf][0] *= al0; O[nf][1] *= al0;
            O[nf][2] *= al1; O[nf][3] *= al1;
        }

        // ---- barrier: all warps done reading Ks; safe to overwrite with P ----
        __syncthreads();

        // ---- P -> smem (half2), warp-private rows of aliased buffer ----
#pragma unroll
        for (int nf = 0; nf < 8; nf++) {
            Ps2[(w16 + lr    ) * ASTR2 + nf * 4 + lc] = packh2(c[nf][0], c[nf][1]);
            Ps2[(w16 + lr + 8) * ASTR2 + nf * 4 + lc] = packh2(c[nf][2], c[nf][3]);
        }
        __syncwarp();

        // ---- O += P V : A = P rows (token k), B = Vt[d][token] ----
#pragma unroll
        for (int kk2 = 0; kk2 < 32; kk2 += 8) {
            uint32_t a0 = Ps2[(w16 + lr    ) * ASTR2 + kk2 + lc    ];
            uint32_t a1 = Ps2[(w16 + lr + 8) * ASTR2 + kk2 + lc    ];
            uint32_t a2 = Ps2[(w16 + lr    ) * ASTR2 + kk2 + lc + 4];
            uint32_t a3 = Ps2[(w16 + lr + 8) * ASTR2 + kk2 + lc + 4];
#pragma unroll
            for (int nf = 0; nf < 8; nf++) {
                uint32_t b0 = Vs2[(nf * 8 + lr) * ASTR2 + kk2 + lc    ];
                uint32_t b1 = Vs2[(nf * 8 + lr) * ASTR2 + kk2 + lc + 4];
                mma16(O[nf], a0, a1, a2, a3, b0, b1);
            }
        }
    }

    // ---- epilogue: normalize, write fp16 to g_attn (gemm1 reads raw) ----
    const float inv0 = 1.f / l0;
    const float inv1 = 1.f / l1;
#pragma unroll
    for (int nf = 0; nf < 8; nf++) {
        int col = h * HS + nf * 8 + 2 * lc;
        *(uint32_t*)&g_attn[(size_t)(qi0 + w16 + lr    ) * DMODEL + col] =
            packh2(O[nf][0] * inv0, O[nf][1] * inv0);
        *(uint32_t*)&g_attn[(size_t)(qi0 + w16 + lr + 8) * DMODEL + col] =
            packh2(O[nf][2] * inv1, O[nf][3] * inv1);
    }
}

// ---------------------------------------------------------------------------
extern "C" void kernel_launch(void* const* d_in, const int* in_sizes, int n_in,
                              void* d_out, int out_size)
{
    const float* x     = (const float*)d_in[0];
    const float* w_qkv = (const float*)d_in[1];
    const float* b_qkv = (const float*)d_in[2];
    const float* w_o   = (const float*)d_in[3];
    const float* b_o   = (const float*)d_in[4];
    const int*   cmask = (n_in > 5) ? (const int*)d_in[5] : nullptr;

    gemm_h<0><<<dim3(3072 / 128, SEQ / 128), 256>>>(x, w_qkv, b_qkv, nullptr);
    attn_h<<<dim3(SEQ / 64, NH), 128>>>(cmask);
    gemm_h<1><<<dim3(DMODEL / 128, SEQ / 128), 256>>>(nullptr, w_o, b_o,
                                                      (float*)d_out);
}

// round 9
// speedup vs baseline: 1.9107x; 1.1504x over previous
#include <cuda_runtime.h>
#include <cuda_fp16.h>
#include <math.h>
#include <stdint.h>

#define SEQ    4096
#define DMODEL 1024
#define NH     16
#define HS     64

// Scratch (no cudaMalloc). fp16 copies of inputs (prepass), Q/K head-major,
// Vt transposed [h][d][tok], attn out fp16 [tok][1024].
__device__ __half g_xh[SEQ * DMODEL];
__device__ __half g_wqh[3 * DMODEL * DMODEL];
__device__ __half g_woh[DMODEL * DMODEL];
__device__ __half g_Q[NH * SEQ * HS];
__device__ __half g_K[NH * SEQ * HS];
__device__ __half g_Vt[NH * HS * SEQ];
__device__ __half g_attn[SEQ * DMODEL];

__device__ __forceinline__ uint32_t packh2(float x, float y) {
    __half2 h = __float22half2_rn(make_float2(x, y));
    return *(uint32_t*)&h;
}

__device__ __forceinline__ void mma16(float* c,
    uint32_t a0, uint32_t a1, uint32_t a2, uint32_t a3,
    uint32_t b0, uint32_t b1)
{
    asm volatile(
        "mma.sync.aligned.m16n8k16.row.col.f32.f16.f16.f32 "
        "{%0,%1,%2,%3},{%4,%5,%6,%7},{%8,%9},{%0,%1,%2,%3};"
        : "+f"(c[0]), "+f"(c[1]), "+f"(c[2]), "+f"(c[3])
        : "r"(a0), "r"(a1), "r"(a2), "r"(a3), "r"(b0), "r"(b1));
}

__device__ __forceinline__ uint32_t s2u(const void* p) {
    return (uint32_t)__cvta_generic_to_shared(p);
}
__device__ __forceinline__ void cp16(uint32_t saddr, const void* gptr) {
    asm volatile("cp.async.cg.shared.global [%0], [%1], 16;"
                 :: "r"(saddr), "l"(gptr));
}
#define CP_COMMIT() asm volatile("cp.async.commit_group;")
#define CP_WAIT2()  asm volatile("cp.async.wait_group 2;")
#define CP_WAIT1()  asm volatile("cp.async.wait_group 1;")
#define CP_WAIT0()  asm volatile("cp.async.wait_group 0;")

// ---------------------------------------------------------------------------
// Pre-pass: fp32 -> fp16 copies of x, w_qkv, w_o (one-time, ~50MB traffic).
// Same rounding as the previous inline cvt -> numerics unchanged.
// ---------------------------------------------------------------------------
__global__ __launch_bounds__(512) void prepass(
    const float* __restrict__ x, const float* __restrict__ wqkv,
    const float* __restrict__ wo)
{
    const int N4x = (SEQ * DMODEL) / 4;
    const int N4q = (3 * DMODEL * DMODEL) / 4;
    const int N4o = (DMODEL * DMODEL) / 4;
    const int total = N4x + N4q + N4o;
    int i = blockIdx.x * blockDim.x + threadIdx.x;
    for (; i < total; i += gridDim.x * blockDim.x) {
        const float4* src; __half* dst; int k;
        if (i < N4x)            { src = (const float4*)x;    dst = g_xh;  k = i; }
        else if (i < N4x + N4q) { src = (const float4*)wqkv; dst = g_wqh; k = i - N4x; }
        else                    { src = (const float4*)wo;   dst = g_woh; k = i - N4x - N4q; }
        float4 v = src[k];
        uint2 h;
        h.x = packh2(v.x, v.y);
        h.y = packh2(v.z, v.w);
        *(uint2*)&dst[(size_t)k * 4] = h;
    }
}

// ---------------------------------------------------------------------------
// fp16 tensor-core GEMM with 4-stage cp.async pipeline.
// C[M,N] = A[M,1024] * B[N,1024]^T + bias[N]
// MODE 0: A = g_xh,   B = g_wqh, scatter to g_Q/g_K/g_Vt (N = 3072)
// MODE 1: A = g_attn, B = g_woh, write fp32 C = d_out   (N = 1024)
// 128x128 block, BK=32, 256 threads (8 warps), warp tile 64x32, m16n8k16.
// Smem rows: 32 data halves + 8 pad = stride 20 uint32 (80B, 16B-multiple);
// fragment LDS pattern (lr*20+lc[+4]) mod 32 -> 32 distinct banks.
// One __syncthreads per K-iter: issue into the buffer consumed at iter i-1
// is safe right after the barrier (all warps finished reading it).
// ---------------------------------------------------------------------------
#define GTILE  (128 * 20)            // uint32 per operand tile
#define GSTAGE (2 * GTILE)           // A + B
#define NSTAGE 4
#define GEMM_SMEM (NSTAGE * GSTAGE * 4)   // 81920 bytes

__device__ __forceinline__ void g_issue(uint32_t* smbase, int s,
    const __half* Asrc, const __half* Bsrc, int bm, int bn, int k0, int t)
{
    uint32_t* As = smbase + s * GSTAGE;
    uint32_t* Bs = As + GTILE;
#pragma unroll
    for (int j = 0; j < 4; j++) {
        int idx  = t + j * 256;          // 1024 chunks of 16B
        int op   = idx >> 9;             // 0 = A, 1 = B (512 each)
        int cidx = idx & 511;
        int row  = cidx >> 2;
        int ch   = cidx & 3;             // 16B chunk within row
        uint32_t* dst = (op ? Bs : As) + row * 20 + ch * 4;
        const __half* src = (op ? Bsrc + (size_t)(bn + row) * DMODEL
                                : Asrc + (size_t)(bm + row) * DMODEL) + k0 + ch * 8;
        cp16(s2u(dst), src);
    }
    CP_COMMIT();
}

template <int MODE>
__global__ __launch_bounds__(256) void gemm_h(
    const float* __restrict__ bias, float* __restrict__ C)
{
    extern __shared__ uint32_t smg[];
    const __half* Asrc = MODE ? g_attn : g_xh;
    const __half* Bsrc = MODE ? g_woh  : g_wqh;
    const int bm = blockIdx.y * 128;
    const int bn = blockIdx.x * 128;
    const int t    = threadIdx.x;
    const int warp = t >> 5;
    const int lane = t & 31;
    const int wm = (warp >> 2) * 64;
    const int wn = (warp & 3) * 32;
    const int lr = lane >> 2;
    const int lc = lane & 3;

    float c[4][4][4];
#pragma unroll
    for (int mf = 0; mf < 4; mf++)
#pragma unroll
        for (int nf = 0; nf < 4; nf++)
#pragma unroll
            for (int r = 0; r < 4; r++) c[mf][nf][r] = 0.f;

    const int KT = DMODEL / 32;          // 32 iterations
    g_issue(smg, 0, Asrc, Bsrc, bm, bn, 0,  t);
    g_issue(smg, 1, Asrc, Bsrc, bm, bn, 32, t);
    g_issue(smg, 2, Asrc, Bsrc, bm, bn, 64, t);

    for (int i = 0; i < KT; i++) {
        int rem = KT - 1 - i;
        if (rem >= 2) CP_WAIT2(); else if (rem == 1) CP_WAIT1(); else CP_WAIT0();
        __syncthreads();

        if (i + 3 < KT)                  // into buffer freed at iter i-1
            g_issue(smg, (i + 3) & 3, Asrc, Bsrc, bm, bn, (i + 3) * 32, t);

        const uint32_t* As2 = smg + (i & 3) * GSTAGE;
        const uint32_t* Bs2 = As2 + GTILE;

#pragma unroll
        for (int kk2 = 0; kk2 < 16; kk2 += 8) {
            uint32_t a[4][4], b[4][2];
#pragma unroll
            for (int mf = 0; mf < 4; mf++) {
                int m0 = wm + mf * 16 + lr;
                a[mf][0] = As2[(m0    ) * 20 + kk2 + lc    ];
                a[mf][1] = As2[(m0 + 8) * 20 + kk2 + lc    ];
                a[mf][2] = As2[(m0    ) * 20 + kk2 + lc + 4];
                a[mf][3] = As2[(m0 + 8) * 20 + kk2 + lc + 4];
            }
#pragma unroll
            for (int nf = 0; nf < 4; nf++) {
                int n0 = wn + nf * 8 + lr;
                b[nf][0] = Bs2[n0 * 20 + kk2 + lc    ];
                b[nf][1] = Bs2[n0 * 20 + kk2 + lc + 4];
            }
#pragma unroll
            for (int mf = 0; mf < 4; mf++)
#pragma unroll
                for (int nf = 0; nf < 4; nf++)
                    mma16(c[mf][nf], a[mf][0], a[mf][1], a[mf][2], a[mf][3],
                          b[nf][0], b[nf][1]);
        }
    }

#pragma unroll
    for (int mf = 0; mf < 4; mf++) {
#pragma unroll
        for (int nf = 0; nf < 4; nf++) {
            int n = bn + wn + nf * 8 + 2 * lc;
            float b0 = bias[n], b1 = bias[n + 1];
#pragma unroll
            for (int rh = 0; rh < 2; rh++) {
                int m = bm + wm + mf * 16 + lr + rh * 8;
                float vx = c[mf][nf][rh * 2 + 0] + b0;
                float vy = c[mf][nf][rh * 2 + 1] + b1;
                if (MODE == 0) {
                    int sel = n >> 10;
                    int nn  = n & 1023;
                    int hd  = nn >> 6;
                    int d   = nn & 63;
                    if (sel < 2) {
                        __half* dst = (sel == 0) ? g_Q : g_K;
                        uint32_t h = packh2(vx, vy);
                        *(uint32_t*)&dst[((size_t)hd * SEQ + m) * HS + d] = h;
                    } else {
                        g_Vt[((size_t)hd * HS + d    ) * SEQ + m] = __float2half_rn(vx);
                        g_Vt[((size_t)hd * HS + d + 1) * SEQ + m] = __float2half_rn(vy);
                    }
                } else {
                    float2 v; v.x = vx; v.y = vy;
                    *(float2*)&C[(size_t)m * DMODEL + n] = v;
                }
            }
        }
    }
}

// ---------------------------------------------------------------------------
// fp16 flash attention — unchanged from R7 (known-good ~173us).
// ---------------------------------------------------------------------------
#define ASTR2 36   // half2 stride per 64-wide row (64 + 8 pad halves)

__global__ __launch_bounds__(128) void attn_h(const int* __restrict__ cmask)
{
    __shared__ uint32_t Qs2[64 * ASTR2];
    __shared__ uint32_t Ks2[64 * ASTR2];   // P aliases this
    __shared__ uint32_t Vs2[64 * ASTR2];   // holds Vt tile: [d][token]
    uint32_t* Ps2 = Ks2;

    const int h   = blockIdx.y;
    const int it  = gridDim.x - 1 - blockIdx.x;   // big tiles first
    const int qi0 = it * 64;
    const int t    = threadIdx.x;
    const int warp = t >> 5;
    const int lane = t & 31;
    const int lr = lane >> 2;
    const int lc = lane & 3;
    const int w16 = warp * 16;
    const int causal = cmask ? cmask[0] : 1;

    {
        const __half* src = g_Q + ((size_t)h * SEQ + qi0) * HS;
#pragma unroll
        for (int j = 0; j < 4; j++) {
            int idx = t + j * 128;
            int row = idx >> 3;
            int col = (idx & 7) * 8;
            *(uint4*)&Qs2[row * ASTR2 + col / 2] =
                *(const uint4*)(src + (size_t)row * HS + col);
        }
    }

    float mrow0 = -INFINITY, mrow1 = -INFINITY, l0 = 0.f, l1 = 0.f;
    float O[8][4];
#pragma unroll
    for (int nf = 0; nf < 8; nf++)
#pragma unroll
        for (int r = 0; r < 4; r++) O[nf][r] = 0.f;

    const int jt_end = causal ? it : (SEQ / 64 - 1);
    for (int jt = 0; jt <= jt_end; jt++) {
        __syncthreads();
        {
            const __half* ksrc = g_K + ((size_t)h * SEQ + jt * 64) * HS;
            const __half* vsrc = g_Vt + (size_t)h * HS * SEQ + jt * 64;
#pragma unroll
            for (int j = 0; j < 4; j++) {
                int idx = t + j * 128;
                int row = idx >> 3;
                int col = (idx & 7) * 8;
                *(uint4*)&Ks2[row * ASTR2 + col / 2] =
                    *(const uint4*)(ksrc + (size_t)row * HS + col);
                *(uint4*)&Vs2[row * ASTR2 + col / 2] =
                    *(const uint4*)(vsrc + (size_t)row * SEQ + col);
            }
        }
        __syncthreads();

        float c[8][4];
#pragma unroll
        for (int nf = 0; nf < 8; nf++)
#pragma unroll
            for (int r = 0; r < 4; r++) c[nf][r] = 0.f;

#pragma unroll
        for (int kk2 = 0; kk2 < 32; kk2 += 8) {
            uint32_t a0 = Qs2[(w16 + lr    ) * ASTR2 + kk2 + lc    ];
            uint32_t a1 = Qs2[(w16 + lr + 8) * ASTR2 + kk2 + lc    ];
            uint32_t a2 = Qs2[(w16 + lr    ) * ASTR2 + kk2 + lc + 4];
            uint32_t a3 = Qs2[(w16 + lr + 8) * ASTR2 + kk2 + lc + 4];
#pragma unroll
            for (int nf = 0; nf < 8; nf++) {
                uint32_t b0 = Ks2[(nf * 8 + lr) * ASTR2 + kk2 + lc    ];
                uint32_t b1 = Ks2[(nf * 8 + lr) * ASTR2 + kk2 + lc + 4];
                mma16(c[nf], a0, a1, a2, a3, b0, b1);
            }
        }

        const bool diag = causal && (jt == it);
        const int row0 = qi0 + w16 + lr;
        const int row1 = row0 + 8;
#pragma unroll
        for (int nf = 0; nf < 8; nf++) {
            int col = jt * 64 + nf * 8 + 2 * lc;
            c[nf][0] *= 0.125f; c[nf][1] *= 0.125f;
            c[nf][2] *= 0.125f; c[nf][3] *= 0.125f;
            if (diag) {
                if (col     > row0) c[nf][0] = -INFINITY;
                if (col + 1 > row0) c[nf][1] = -INFINITY;
                if (col     > row1) c[nf][2] = -INFINITY;
                if (col + 1 > row1) c[nf][3] = -INFINITY;
            }
        }

        float mx0 = -INFINITY, mx1 = -INFINITY;
#pragma unroll
        for (int nf = 0; nf < 8; nf++) {
            mx0 = fmaxf(mx0, fmaxf(c[nf][0], c[nf][1]));
            mx1 = fmaxf(mx1, fmaxf(c[nf][2], c[nf][3]));
        }
        mx0 = fmaxf(mx0, __shfl_xor_sync(0xffffffffu, mx0, 1));
        mx0 = fmaxf(mx0, __shfl_xor_sync(0xffffffffu, mx0, 2));
        mx1 = fmaxf(mx1, __shfl_xor_sync(0xffffffffu, mx1, 1));
        mx1 = fmaxf(mx1, __shfl_xor_sync(0xffffffffu, mx1, 2));

        const float mn0 = fmaxf(mrow0, mx0);
        const float mn1 = fmaxf(mrow1, mx1);
        const float al0 = __expf(mrow0 - mn0);
        const float al1 = __expf(mrow1 - mn1);
        float s0 = 0.f, s1 = 0.f;
#pragma unroll
        for (int nf = 0; nf < 8; nf++) {
            c[nf][0] = __expf(c[nf][0] - mn0); s0 += c[nf][0];
            c[nf][1] = __expf(c[nf][1] - mn0); s0 += c[nf][1];
            c[nf][2] = __expf(c[nf][2] - mn1); s1 += c[nf][2];
            c[nf][3] = __expf(c[nf][3] - mn1); s1 += c[nf][3];
        }
        s0 += __shfl_xor_sync(0xffffffffu, s0, 1);
        s0 += __shfl_xor_sync(0xffffffffu, s0, 2);
        s1 += __shfl_xor_sync(0xffffffffu, s1, 1);
        s1 += __shfl_xor_sync(0xffffffffu, s1, 2);
        l0 = l0 * al0 + s0;  l1 = l1 * al1 + s1;
        mrow0 = mn0;         mrow1 = mn1;
#pragma unroll
        for (int nf = 0; nf < 8; nf++) {
            O[nf][0] *= al0; O[nf][1] *= al0;
            O[nf][2] *= al1; O[nf][3] *= al1;
        }

        __syncthreads();   // all warps done reading Ks; safe to alias with P

#pragma unroll
        for (int nf = 0; nf < 8; nf++) {
            Ps2[(w16 + lr    ) * ASTR2 + nf * 4 + lc] = packh2(c[nf][0], c[nf][1]);
            Ps2[(w16 + lr + 8) * ASTR2 + nf * 4 + lc] = packh2(c[nf][2], c[nf][3]);
        }
        __syncwarp();

#pragma unroll
        for (int kk2 = 0; kk2 < 32; kk2 += 8) {
            uint32_t a0 = Ps2[(w16 + lr    ) * ASTR2 + kk2 + lc    ];
            uint32_t a1 = Ps2[(w16 + lr + 8) * ASTR2 + kk2 + lc    ];
            uint32_t a2 = Ps2[(w16 + lr    ) * ASTR2 + kk2 + lc + 4];
            uint32_t a3 = Ps2[(w16 + lr + 8) * ASTR2 + kk2 + lc + 4];
#pragma unroll
            for (int nf = 0; nf < 8; nf++) {
                uint32_t b0 = Vs2[(nf * 8 + lr) * ASTR2 + kk2 + lc    ];
                uint32_t b1 = Vs2[(nf * 8 + lr) * ASTR2 + kk2 + lc + 4];
                mma16(O[nf], a0, a1, a2, a3, b0, b1);
            }
        }
    }

    const float inv0 = 1.f / l0;
    const float inv1 = 1.f / l1;
#pragma unroll
    for (int nf = 0; nf < 8; nf++) {
        int col = h * HS + nf * 8 + 2 * lc;
        *(uint32_t*)&g_attn[(size_t)(qi0 + w16 + lr    ) * DMODEL + col] =
            packh2(O[nf][0] * inv0, O[nf][1] * inv0);
        *(uint32_t*)&g_attn[(size_t)(qi0 + w16 + lr + 8) * DMODEL + col] =
            packh2(O[nf][2] * inv1, O[nf][3] * inv1);
    }
}

// ---------------------------------------------------------------------------
extern "C" void kernel_launch(void* const* d_in, const int* in_sizes, int n_in,
                              void* d_out, int out_size)
{
    const float* x     = (const float*)d_in[0];
    const float* w_qkv = (const float*)d_in[1];
    const float* b_qkv = (const float*)d_in[2];
    const float* w_o   = (const float*)d_in[3];
    const float* b_o   = (const float*)d_in[4];
    const int*   cmask = (n_in > 5) ? (const int*)d_in[5] : nullptr;

    cudaFuncSetAttribute(gemm_h<0>,
                         cudaFuncAttributeMaxDynamicSharedMemorySize, GEMM_SMEM);
    cudaFuncSetAttribute(gemm_h<1>,
                         cudaFuncAttributeMaxDynamicSharedMemorySize, GEMM_SMEM);

    prepass<<<1024, 512>>>(x, w_qkv, w_o);
    gemm_h<0><<<dim3(3072 / 128, SEQ / 128), 256, GEMM_SMEM>>>(b_qkv, nullptr);
    attn_h<<<dim3(SEQ / 64, NH), 128>>>(cmask);
    gemm_h<1><<<dim3(DMODEL / 128, SEQ / 128), 256, GEMM_SMEM>>>(b_o,
                                                                 (float*)d_out);
}

// round 10
// speedup vs baseline: 1.9733x; 1.0328x over previous
#include <cuda_runtime.h>
#include <cuda_fp16.h>
#include <math.h>
#include <stdint.h>

#define SEQ    4096
#define DMODEL 1024
#define NH     16
#define HS     64

// Scratch (no cudaMalloc). fp16 copies of inputs (prepass), Q/K head-major,
// Vt transposed [h][d][tok], attn out fp16 [tok][1024].
__device__ __half g_xh[SEQ * DMODEL];
__device__ __half g_wqh[3 * DMODEL * DMODEL];
__device__ __half g_woh[DMODEL * DMODEL];
__device__ __half g_Q[NH * SEQ * HS];
__device__ __half g_K[NH * SEQ * HS];
__device__ __half g_Vt[NH * HS * SEQ];
__device__ __half g_attn[SEQ * DMODEL];

__device__ __forceinline__ uint32_t packh2(float x, float y) {
    __half2 h = __float22half2_rn(make_float2(x, y));
    return *(uint32_t*)&h;
}

__device__ __forceinline__ void mma16(float* c,
    uint32_t a0, uint32_t a1, uint32_t a2, uint32_t a3,
    uint32_t b0, uint32_t b1)
{
    asm volatile(
        "mma.sync.aligned.m16n8k16.row.col.f32.f16.f16.f32 "
        "{%0,%1,%2,%3},{%4,%5,%6,%7},{%8,%9},{%0,%1,%2,%3};"
        : "+f"(c[0]), "+f"(c[1]), "+f"(c[2]), "+f"(c[3])
        : "r"(a0), "r"(a1), "r"(a2), "r"(a3), "r"(b0), "r"(b1));
}

__device__ __forceinline__ uint32_t s2u(const void* p) {
    return (uint32_t)__cvta_generic_to_shared(p);
}
__device__ __forceinline__ void ldsm4(uint32_t& r0, uint32_t& r1,
                                      uint32_t& r2, uint32_t& r3, uint32_t addr)
{
    asm volatile("ldmatrix.sync.aligned.m8n8.x4.shared.b16 {%0,%1,%2,%3}, [%4];"
                 : "=r"(r0), "=r"(r1), "=r"(r2), "=r"(r3) : "r"(addr));
}
__device__ __forceinline__ void cp16(uint32_t saddr, const void* gptr) {
    asm volatile("cp.async.cg.shared.global [%0], [%1], 16;"
                 :: "r"(saddr), "l"(gptr));
}
#define CP_COMMIT() asm volatile("cp.async.commit_group;")
#define CP_WAIT2()  asm volatile("cp.async.wait_group 2;")
#define CP_WAIT1()  asm volatile("cp.async.wait_group 1;")
#define CP_WAIT0()  asm volatile("cp.async.wait_group 0;")

// ---------------------------------------------------------------------------
// Pre-pass: fp32 -> fp16 copies of x, w_qkv, w_o (one-time, ~50MB traffic).
// ---------------------------------------------------------------------------
__global__ __launch_bounds__(512) void prepass(
    const float* __restrict__ x, const float* __restrict__ wqkv,
    const float* __restrict__ wo)
{
    const int N4x = (SEQ * DMODEL) / 4;
    const int N4q = (3 * DMODEL * DMODEL) / 4;
    const int N4o = (DMODEL * DMODEL) / 4;
    const int total = N4x + N4q + N4o;
    int i = blockIdx.x * blockDim.x + threadIdx.x;
    for (; i < total; i += gridDim.x * blockDim.x) {
        const float4* src; __half* dst; int k;
        if (i < N4x)            { src = (const float4*)x;    dst = g_xh;  k = i; }
        else if (i < N4x + N4q) { src = (const float4*)wqkv; dst = g_wqh; k = i - N4x; }
        else                    { src = (const float4*)wo;   dst = g_woh; k = i - N4x - N4q; }
        float4 v = src[k];
        uint2 h;
        h.x = packh2(v.x, v.y);
        h.y = packh2(v.z, v.w);
        *(uint2*)&dst[(size_t)k * 4] = h;
    }
}

// ---------------------------------------------------------------------------
// fp16 tensor-core GEMM, 4-stage cp.async pipeline + ldmatrix fragments.
// C[M,N] = A[M,1024] * B[N,1024]^T + bias[N]
// MODE 0: A = g_xh,   B = g_wqh, scatter to g_Q/g_K/g_Vt (N = 3072)
// MODE 1: A = g_attn, B = g_woh, write fp32 C = d_out   (N = 1024)
// Smem rows stride 20 uint32 (80B): LDSM 8-row phase = 5r mod 8 -> no conflict.
// ---------------------------------------------------------------------------
#define GTILE  (128 * 20)
#define GSTAGE (2 * GTILE)
#define NSTAGE 4
#define GEMM_SMEM (NSTAGE * GSTAGE * 4)   // 81920 bytes

__device__ __forceinline__ void g_issue(uint32_t* smbase, int s,
    const __half* Asrc, const __half* Bsrc, int bm, int bn, int k0, int t)
{
    uint32_t* As = smbase + s * GSTAGE;
    uint32_t* Bs = As + GTILE;
#pragma unroll
    for (int j = 0; j < 4; j++) {
        int idx  = t + j * 256;
        int op   = idx >> 9;
        int cidx = idx & 511;
        int row  = cidx >> 2;
        int ch   = cidx & 3;
        uint32_t* dst = (op ? Bs : As) + row * 20 + ch * 4;
        const __half* src = (op ? Bsrc + (size_t)(bn + row) * DMODEL
                                : Asrc + (size_t)(bm + row) * DMODEL) + k0 + ch * 8;
        cp16(s2u(dst), src);
    }
    CP_COMMIT();
}

template <int MODE>
__global__ __launch_bounds__(256) void gemm_h(
    const float* __restrict__ bias, float* __restrict__ C)
{
    extern __shared__ uint32_t smg[];
    const __half* Asrc = MODE ? g_attn : g_xh;
    const __half* Bsrc = MODE ? g_woh  : g_wqh;
    const int bm = blockIdx.y * 128;
    const int bn = blockIdx.x * 128;
    const int t    = threadIdx.x;
    const int warp = t >> 5;
    const int lane = t & 31;
    const int wm = (warp >> 2) * 64;
    const int wn = (warp & 3) * 32;
    const int lr = lane >> 2;
    const int lc = lane & 3;
    const int lm16  = lane & 15;          // ldmatrix row-within-16
    const int lk4   = (lane >> 4) * 4;    // ldmatrix k-chunk select

    float c[4][4][4];
#pragma unroll
    for (int mf = 0; mf < 4; mf++)
#pragma unroll
        for (int nf = 0; nf < 4; nf++)
#pragma unroll
            for (int r = 0; r < 4; r++) c[mf][nf][r] = 0.f;

    const int KT = DMODEL / 32;
    g_issue(smg, 0, Asrc, Bsrc, bm, bn, 0,  t);
    g_issue(smg, 1, Asrc, Bsrc, bm, bn, 32, t);
    g_issue(smg, 2, Asrc, Bsrc, bm, bn, 64, t);

    for (int i = 0; i < KT; i++) {
        int rem = KT - 1 - i;
        if (rem >= 2) CP_WAIT2(); else if (rem == 1) CP_WAIT1(); else CP_WAIT0();
        __syncthreads();

        if (i + 3 < KT)
            g_issue(smg, (i + 3) & 3, Asrc, Bsrc, bm, bn, (i + 3) * 32, t);

        const uint32_t* As2 = smg + (i & 3) * GSTAGE;
        const uint32_t* Bs2 = As2 + GTILE;

#pragma unroll
        for (int kk2 = 0; kk2 < 16; kk2 += 8) {
            uint32_t a[4][4], b[4][2];
#pragma unroll
            for (int mf = 0; mf < 4; mf++)
                ldsm4(a[mf][0], a[mf][1], a[mf][2], a[mf][3],
                      s2u(&As2[(wm + mf * 16 + lm16) * 20 + kk2 + lk4]));
#pragma unroll
            for (int nf2 = 0; nf2 < 2; nf2++) {
                uint32_t r0, r1, r2, r3;
                ldsm4(r0, r1, r2, r3,
                      s2u(&Bs2[(wn + nf2 * 16 + lm16) * 20 + kk2 + lk4]));
                b[2 * nf2    ][0] = r0; b[2 * nf2    ][1] = r2;
                b[2 * nf2 + 1][0] = r1; b[2 * nf2 + 1][1] = r3;
            }
#pragma unroll
            for (int mf = 0; mf < 4; mf++)
#pragma unroll
                for (int nf = 0; nf < 4; nf++)
                    mma16(c[mf][nf], a[mf][0], a[mf][1], a[mf][2], a[mf][3],
                          b[nf][0], b[nf][1]);
        }
    }

#pragma unroll
    for (int mf = 0; mf < 4; mf++) {
#pragma unroll
        for (int nf = 0; nf < 4; nf++) {
            int n = bn + wn + nf * 8 + 2 * lc;
            float b0 = bias[n], b1 = bias[n + 1];
#pragma unroll
            for (int rh = 0; rh < 2; rh++) {
                int m = bm + wm + mf * 16 + lr + rh * 8;
                float vx = c[mf][nf][rh * 2 + 0] + b0;
                float vy = c[mf][nf][rh * 2 + 1] + b1;
                if (MODE == 0) {
                    int sel = n >> 10;
                    int nn  = n & 1023;
                    int hd  = nn >> 6;
                    int d   = nn & 63;
                    if (sel < 2) {
                        __half* dst = (sel == 0) ? g_Q : g_K;
                        uint32_t h = packh2(vx, vy);
                        *(uint32_t*)&dst[((size_t)hd * SEQ + m) * HS + d] = h;
                    } else {
                        g_Vt[((size_t)hd * HS + d    ) * SEQ + m] = __float2half_rn(vx);
                        g_Vt[((size_t)hd * HS + d + 1) * SEQ + m] = __float2half_rn(vy);
                    }
                } else {
                    float2 v; v.x = vx; v.y = vy;
                    *(float2*)&C[(size_t)m * DMODEL + n] = v;
                }
            }
        }
    }
}

// ---------------------------------------------------------------------------
// fp16 flash attention, register-resident P + ldmatrix fragments.
// Grid (S/64, NH), 128 threads (4 warps). Warp w owns q-rows [w*16, w*16+16).
// P never touches smem: the QK C-fragment layout equals the PV A-fragment
// layout (C col nf*8+2lc == PV token 16*k2+{0,8}+2lc for nf = 2k2, 2k2+1).
// Smem stride 36 uint32 (144B): LDSM 8-row phase = r mod 8 -> conflict-free.
// ---------------------------------------------------------------------------
#define ASTR2 36

__global__ __launch_bounds__(128) void attn_h(const int* __restrict__ cmask)
{
    __shared__ uint32_t Qs2[64 * ASTR2];
    __shared__ uint32_t Ks2[64 * ASTR2];
    __shared__ uint32_t Vs2[64 * ASTR2];   // Vt tile: [d][token]

    const int h   = blockIdx.y;
    const int it  = gridDim.x - 1 - blockIdx.x;   // big tiles first
    const int qi0 = it * 64;
    const int t    = threadIdx.x;
    const int warp = t >> 5;
    const int lane = t & 31;
    const int lr = lane >> 2;
    const int lc = lane & 3;
    const int w16 = warp * 16;
    const int lm16 = lane & 15;
    const int lk4  = (lane >> 4) * 4;
    const int causal = cmask ? cmask[0] : 1;

    {
        const __half* src = g_Q + ((size_t)h * SEQ + qi0) * HS;
#pragma unroll
        for (int j = 0; j < 4; j++) {
            int idx = t + j * 128;
            int row = idx >> 3;
            int col = (idx & 7) * 8;
            *(uint4*)&Qs2[row * ASTR2 + col / 2] =
                *(const uint4*)(src + (size_t)row * HS + col);
        }
    }

    float mrow0 = -INFINITY, mrow1 = -INFINITY, l0 = 0.f, l1 = 0.f;
    float O[8][4];
#pragma unroll
    for (int nf = 0; nf < 8; nf++)
#pragma unroll
        for (int r = 0; r < 4; r++) O[nf][r] = 0.f;

    const int jt_end = causal ? it : (SEQ / 64 - 1);
    for (int jt = 0; jt <= jt_end; jt++) {
        __syncthreads();                 // prev iter done with Ks/Vs
        {
            const __half* ksrc = g_K + ((size_t)h * SEQ + jt * 64) * HS;
            const __half* vsrc = g_Vt + (size_t)h * HS * SEQ + jt * 64;
#pragma unroll
            for (int j = 0; j < 4; j++) {
                int idx = t + j * 128;
                int row = idx >> 3;
                int col = (idx & 7) * 8;
                *(uint4*)&Ks2[row * ASTR2 + col / 2] =
                    *(const uint4*)(ksrc + (size_t)row * HS + col);
                *(uint4*)&Vs2[row * ASTR2 + col / 2] =
                    *(const uint4*)(vsrc + (size_t)row * SEQ + col);
            }
        }
        __syncthreads();

        // ---- S = Q K^T (16x64 per warp), ldmatrix fragments ----
        float c[8][4];
#pragma unroll
        for (int nf = 0; nf < 8; nf++)
#pragma unroll
            for (int r = 0; r < 4; r++) c[nf][r] = 0.f;

#pragma unroll
        for (int kk2 = 0; kk2 < 32; kk2 += 8) {
            uint32_t a0, a1, a2, a3;
            ldsm4(a0, a1, a2, a3,
                  s2u(&Qs2[(w16 + lm16) * ASTR2 + kk2 + lk4]));
#pragma unroll
            for (int nf2 = 0; nf2 < 4; nf2++) {
                uint32_t r0, r1, r2, r3;
                ldsm4(r0, r1, r2, r3,
                      s2u(&Ks2[(nf2 * 16 + lm16) * ASTR2 + kk2 + lk4]));
                mma16(c[2 * nf2    ], a0, a1, a2, a3, r0, r2);
                mma16(c[2 * nf2 + 1], a0, a1, a2, a3, r1, r3);
            }
        }

        // ---- mask + scale ----
        const bool diag = causal && (jt == it);
        const int row0 = qi0 + w16 + lr;
        const int row1 = row0 + 8;
#pragma unroll
        for (int nf = 0; nf < 8; nf++) {
            int col = jt * 64 + nf * 8 + 2 * lc;
            c[nf][0] *= 0.125f; c[nf][1] *= 0.125f;
            c[nf][2] *= 0.125f; c[nf][3] *= 0.125f;
            if (diag) {
                if (col     > row0) c[nf][0] = -INFINITY;
                if (col + 1 > row0) c[nf][1] = -INFINITY;
                if (col     > row1) c[nf][2] = -INFINITY;
                if (col + 1 > row1) c[nf][3] = -INFINITY;
            }
        }

        // ---- online softmax (rows live in lane quads) ----
        float mx0 = -INFINITY, mx1 = -INFINITY;
#pragma unroll
        for (int nf = 0; nf < 8; nf++) {
            mx0 = fmaxf(mx0, fmaxf(c[nf][0], c[nf][1]));
            mx1 = fmaxf(mx1, fmaxf(c[nf][2], c[nf][3]));
        }
        mx0 = fmaxf(mx0, __shfl_xor_sync(0xffffffffu, mx0, 1));
        mx0 = fmaxf(mx0, __shfl_xor_sync(0xffffffffu, mx0, 2));
        mx1 = fmaxf(mx1, __shfl_xor_sync(0xffffffffu, mx1, 1));
        mx1 = fmaxf(mx1, __shfl_xor_sync(0xffffffffu, mx1, 2));

        const float mn0 = fmaxf(mrow0, mx0);
        const float mn1 = fmaxf(mrow1, mx1);
        const float al0 = __expf(mrow0 - mn0);
        const float al1 = __expf(mrow1 - mn1);
        float s0 = 0.f, s1 = 0.f;
#pragma unroll
        for (int nf = 0; nf < 8; nf++) {
            c[nf][0] = __expf(c[nf][0] - mn0); s0 += c[nf][0];
            c[nf][1] = __expf(c[nf][1] - mn0); s0 += c[nf][1];
            c[nf][2] = __expf(c[nf][2] - mn1); s1 += c[nf][2];
            c[nf][3] = __expf(c[nf][3] - mn1); s1 += c[nf][3];
        }
        s0 += __shfl_xor_sync(0xffffffffu, s0, 1);
        s0 += __shfl_xor_sync(0xffffffffu, s0, 2);
        s1 += __shfl_xor_sync(0xffffffffu, s1, 1);
        s1 += __shfl_xor_sync(0xffffffffu, s1, 2);
        l0 = l0 * al0 + s0;  l1 = l1 * al1 + s1;
        mrow0 = mn0;         mrow1 = mn1;
#pragma unroll
        for (int nf = 0; nf < 8; nf++) {
            O[nf][0] *= al0; O[nf][1] *= al0;
            O[nf][2] *= al1; O[nf][3] *= al1;
        }

        // ---- O += P V, P straight from registers ----
#pragma unroll
        for (int k2 = 0; k2 < 4; k2++) {
            uint32_t a0 = packh2(c[2 * k2    ][0], c[2 * k2    ][1]);
            uint32_t a1 = packh2(c[2 * k2    ][2], c[2 * k2    ][3]);
            uint32_t a2 = packh2(c[2 * k2 + 1][0], c[2 * k2 + 1][1]);
            uint32_t a3 = packh2(c[2 * k2 + 1][2], c[2 * k2 + 1][3]);
#pragma unroll
            for (int nf2 = 0; nf2 < 4; nf2++) {
                uint32_t r0, r1, r2, r3;
                ldsm4(r0, r1, r2, r3,
                      s2u(&Vs2[(nf2 * 16 + lm16) * ASTR2 + 8 * k2 + lk4]));
                mma16(O[2 * nf2    ], a0, a1, a2, a3, r0, r2);
                mma16(O[2 * nf2 + 1], a0, a1, a2, a3, r1, r3);
            }
        }
    }

    // ---- epilogue: normalize, write fp16 to g_attn ----
    const float inv0 = 1.f / l0;
    const float inv1 = 1.f / l1;
#pragma unroll
    for (int nf = 0; nf < 8; nf++) {
        int col = h * HS + nf * 8 + 2 * lc;
        *(uint32_t*)&g_attn[(size_t)(qi0 + w16 + lr    ) * DMODEL + col] =
            packh2(O[nf][0] * inv0, O[nf][1] * inv0);
        *(uint32_t*)&g_attn[(size_t)(qi0 + w16 + lr + 8) * DMODEL + col] =
            packh2(O[nf][2] * inv1, O[nf][3] * inv1);
    }
}

// ---------------------------------------------------------------------------
extern "C" void kernel_launch(void* const* d_in, const int* in_sizes, int n_in,
                              void* d_out, int out_size)
{
    const float* x     = (const float*)d_in[0];
    const float* w_qkv = (const float*)d_in[1];
    const float* b_qkv = (const float*)d_in[2];
    const float* w_o   = (const float*)d_in[3];
    const float* b_o   = (const float*)d_in[4];
    const int*   cmask = (n_in > 5) ? (const int*)d_in[5] : nullptr;

    cudaFuncSetAttribute(gemm_h<0>,
                         cudaFuncAttributeMaxDynamicSharedMemorySize, GEMM_SMEM);
    cudaFuncSetAttribute(gemm_h<1>,
                         cudaFuncAttributeMaxDynamicSharedMemorySize, GEMM_SMEM);

    prepass<<<1024, 512>>>(x, w_qkv, w_o);
    gemm_h<0><<<dim3(3072 / 128, SEQ / 128), 256, GEMM_SMEM>>>(b_qkv, nullptr);
    attn_h<<<dim3(SEQ / 64, NH), 128>>>(cmask);
    gemm_h<1><<<dim3(DMODEL / 128, SEQ / 128), 256, GEMM_SMEM>>>(b_o,
                                                                 (float*)d_out);
}

// round 14
// speedup vs baseline: 2.2528x; 1.1416x over previous
#include <cuda_runtime.h>
#include <cuda_fp16.h>
#include <math.h>
#include <stdint.h>

#define SEQ    4096
#define DMODEL 1024
#define NH     16
#define HS     64

// Scratch (no cudaMalloc). fp16 copies of inputs (prepass), Q/K head-major,
// Vt transposed [h][d][tok], attn out fp16 [tok][1024].
// g_Q is pre-scaled by 0.125*log2(e) so softmax uses bare exp2.
__device__ __half g_xh[SEQ * DMODEL];
__device__ __half g_wqh[3 * DMODEL * DMODEL];
__device__ __half g_woh[DMODEL * DMODEL];
__device__ __half g_Q[NH * SEQ * HS];
__device__ __half g_K[NH * SEQ * HS];
__device__ __half g_Vt[NH * HS * SEQ];
__device__ __half g_attn[SEQ * DMODEL];

#define QSCALE 0.1803368801111244f   // 0.125 * log2(e)

__device__ __forceinline__ uint32_t packh2(float x, float y) {
    __half2 h = __float22half2_rn(make_float2(x, y));
    return *(uint32_t*)&h;
}

__device__ __forceinline__ void mma16(float* c,
    uint32_t a0, uint32_t a1, uint32_t a2, uint32_t a3,
    uint32_t b0, uint32_t b1)
{
    asm volatile(
        "mma.sync.aligned.m16n8k16.row.col.f32.f16.f16.f32 "
        "{%0,%1,%2,%3},{%4,%5,%6,%7},{%8,%9},{%0,%1,%2,%3};"
        : "+f"(c[0]), "+f"(c[1]), "+f"(c[2]), "+f"(c[3])
        : "r"(a0), "r"(a1), "r"(a2), "r"(a3), "r"(b0), "r"(b1));
}

__device__ __forceinline__ uint32_t s2u(const void* p) {
    return (uint32_t)__cvta_generic_to_shared(p);
}
__device__ __forceinline__ void ldsm4(uint32_t& r0, uint32_t& r1,
                                      uint32_t& r2, uint32_t& r3, uint32_t addr)
{
    asm volatile("ldmatrix.sync.aligned.m8n8.x4.shared.b16 {%0,%1,%2,%3}, [%4];"
                 : "=r"(r0), "=r"(r1), "=r"(r2), "=r"(r3) : "r"(addr));
}
__device__ __forceinline__ void cp16(uint32_t saddr, const void* gptr) {
    asm volatile("cp.async.cg.shared.global [%0], [%1], 16;"
                 :: "r"(saddr), "l"(gptr));
}
#define CP_COMMIT() asm volatile("cp.async.commit_group;")
#define CP_WAIT1()  asm volatile("cp.async.wait_group 1;")
#define CP_WAIT0()  asm volatile("cp.async.wait_group 0;")

// ---------------------------------------------------------------------------
// Pre-pass: fp32 -> fp16 copies of x, w_qkv, w_o.
// ---------------------------------------------------------------------------
__global__ __launch_bounds__(512) void prepass(
    const float* __restrict__ x, const float* __restrict__ wqkv,
    const float* __restrict__ wo)
{
    const int N4x = (SEQ * DMODEL) / 4;
    const int N4q = (3 * DMODEL * DMODEL) / 4;
    const int N4o = (DMODEL * DMODEL) / 4;
    const int total = N4x + N4q + N4o;
    int i = blockIdx.x * blockDim.x + threadIdx.x;
    for (; i < total; i += gridDim.x * blockDim.x) {
        const float4* src; __half* dst; int k;
        if (i < N4x)            { src = (const float4*)x;    dst = g_xh;  k = i; }
        else if (i < N4x + N4q) { src = (const float4*)wqkv; dst = g_wqh; k = i - N4x; }
        else                    { src = (const float4*)wo;   dst = g_woh; k = i - N4x - N4q; }
        float4 v = src[k];
        uint2 h;
        h.x = packh2(v.x, v.y);
        h.y = packh2(v.z, v.w);
        *(uint2*)&dst[(size_t)k * 4] = h;
    }
}

// ---------------------------------------------------------------------------
// fp16 GEMM: BK=64, 3-stage cp.async pipeline (16 mainloop barriers instead
// of 32), ldmatrix fragments. Smem row stride 36 u32 (144B): LDSM 8-row
// phase = 9r mod 8 = r -> conflict-free. 110.6KB dyn smem -> 2 CTA/SM.
// MODE 0: A = g_xh,   B = g_wqh, scatter to g_Q(scaled)/g_K/g_Vt (N = 3072)
// MODE 1: A = g_attn, B = g_woh, write fp32 C = d_out (N = 1024)
// ---------------------------------------------------------------------------
#define GSTR   36                    // u32 stride per 64-half row
#define GTILE  (128 * GSTR)
#define GSTAGE (2 * GTILE)
#define NSTAGE 3
#define GEMM_SMEM (NSTAGE * GSTAGE * 4)   // 110592 bytes

__device__ __forceinline__ void g_issue(uint32_t* smbase, int s,
    const __half* Asrc, const __half* Bsrc, int bm, int bn, int k0, int t)
{
    uint32_t* As = smbase + s * GSTAGE;
    uint32_t* Bs = As + GTILE;
#pragma unroll
    for (int j = 0; j < 8; j++) {
        int idx  = t + j * 256;          // 2048 chunks of 16B
        int op   = idx >> 10;            // 0 = A, 1 = B (1024 each)
        int cidx = idx & 1023;
        int row  = cidx >> 3;
        int ch   = cidx & 7;             // 16B chunk within 128B row
        uint32_t* dst = (op ? Bs : As) + row * GSTR + ch * 4;
        const __half* src = (op ? Bsrc + (size_t)(bn + row) * DMODEL
                                : Asrc + (size_t)(bm + row) * DMODEL) + k0 + ch * 8;
        cp16(s2u(dst), src);
    }
    CP_COMMIT();
}

template <int MODE>
__global__ __launch_bounds__(256) void gemm_h(
    const float* __restrict__ bias, float* __restrict__ C)
{
    extern __shared__ uint32_t smg[];
    const __half* Asrc = MODE ? g_attn : g_xh;
    const __half* Bsrc = MODE ? g_woh  : g_wqh;
    const int bm = blockIdx.y * 128;
    const int bn = blockIdx.x * 128;
    const int t    = threadIdx.x;
    const int warp = t >> 5;
    const int lane = t & 31;
    const int wm = (warp >> 2) * 64;
    const int wn = (warp & 3) * 32;
    const int lr = lane >> 2;
    const int lc = lane & 3;
    const int lm16 = lane & 15;
    const int lk4  = (lane >> 4) * 4;

    float c[4][4][4];
#pragma unroll
    for (int mf = 0; mf < 4; mf++)
#pragma unroll
        for (int nf = 0; nf < 4; nf++)
#pragma unroll
            for (int r = 0; r < 4; r++) c[mf][nf][r] = 0.f;

    const int KT = DMODEL / 64;          // 16 iterations
    g_issue(smg, 0, Asrc, Bsrc, bm, bn, 0,  t);
    g_issue(smg, 1, Asrc, Bsrc, bm, bn, 64, t);

    int stage = 0;
    for (int i = 0; i < KT; i++) {
        if (i + 1 < KT) CP_WAIT1(); else CP_WAIT0();
        __syncthreads();

        if (i + 2 < KT) {
            int ns = stage + 2; if (ns >= 3) ns -= 3;
            g_issue(smg, ns, Asrc, Bsrc, bm, bn, (i + 2) * 64, t);
        }

        const uint32_t* As2 = smg + stage * GSTAGE;
        const uint32_t* Bs2 = As2 + GTILE;

#pragma unroll
        for (int kk2 = 0; kk2 < 32; kk2 += 8) {
            uint32_t a[4][4], b[4][2];
#pragma unroll
            for (int mf = 0; mf < 4; mf++)
                ldsm4(a[mf][0], a[mf][1], a[mf][2], a[mf][3],
                      s2u(&As2[(wm + mf * 16 + lm16) * GSTR + kk2 + lk4]));
#pragma unroll
            for (int nf2 = 0; nf2 < 2; nf2++) {
                uint32_t r0, r1, r2, r3;
                ldsm4(r0, r1, r2, r3,
                      s2u(&Bs2[(wn + nf2 * 16 + lm16) * GSTR + kk2 + lk4]));
                b[2 * nf2    ][0] = r0; b[2 * nf2    ][1] = r2;
                b[2 * nf2 + 1][0] = r1; b[2 * nf2 + 1][1] = r3;
            }
#pragma unroll
            for (int mf = 0; mf < 4; mf++)
#pragma unroll
                for (int nf = 0; nf < 4; nf++)
                    mma16(c[mf][nf], a[mf][0], a[mf][1], a[mf][2], a[mf][3],
                          b[nf][0], b[nf][1]);
        }
        if (++stage >= 3) stage = 0;
    }

#pragma unroll
    for (int mf = 0; mf < 4; mf++) {
#pragma unroll
        for (int nf = 0; nf < 4; nf++) {
            int n = bn + wn + nf * 8 + 2 * lc;
            float b0 = bias[n], b1 = bias[n + 1];
#pragma unroll
            for (int rh = 0; rh < 2; rh++) {
                int m = bm + wm + mf * 16 + lr + rh * 8;
                float vx = c[mf][nf][rh * 2 + 0] + b0;
                float vy = c[mf][nf][rh * 2 + 1] + b1;
                if (MODE == 0) {
                    int sel = n >> 10;
                    int nn  = n & 1023;
                    int hd  = nn >> 6;
                    int d   = nn & 63;
                    if (sel == 0) {      // Q: pre-scale for exp2 softmax
                        uint32_t h = packh2(vx * QSCALE, vy * QSCALE);
                        *(uint32_t*)&g_Q[((size_t)hd * SEQ + m) * HS + d] = h;
                    } else if (sel == 1) {
                        uint32_t h = packh2(vx, vy);
                        *(uint32_t*)&g_K[((size_t)hd * SEQ + m) * HS + d] = h;
                    } else {
                        g_Vt[((size_t)hd * HS + d    ) * SEQ + m] = __float2half_rn(vx);
                        g_Vt[((size_t)hd * HS + d + 1) * SEQ + m] = __float2half_rn(vy);
                    }
                } else {
                    float2 v; v.x = vx; v.y = vy;
                    *(float2*)&C[(size_t)m * DMODEL + n] = v;
                }
            }
        }
    }
}

// ---------------------------------------------------------------------------
// fp16 flash attention: register-P + ldmatrix + 2-stage cp.async KV prefetch
// + exp2 softmax (scale folded into Q). Grid (S/64, NH), 128 threads.
// Smem: Q + 2x{K,V} = 46KB static -> 4 CTA/SM.
// ---------------------------------------------------------------------------
#define ASTR2 36

__device__ __forceinline__ void kv_issue(uint32_t* Kst, uint32_t* Vst,
    const __half* kbase, const __half* vbase, int jt, int t)
{
    const __half* kg = kbase + (size_t)jt * 64 * HS;
    const __half* vg = vbase + (size_t)jt * 64;
#pragma unroll
    for (int j = 0; j < 8; j++) {
        int idx = t + j * 128;           // 1024 chunks of 16B
        int op  = idx >> 9;              // 0 = K, 1 = V
        int c   = idx & 511;
        int row = c >> 3;
        int ch  = c & 7;
        if (op == 0)
            cp16(s2u(&Kst[row * ASTR2 + ch * 4]), kg + (size_t)row * HS + ch * 8);
        else
            cp16(s2u(&Vst[row * ASTR2 + ch * 4]), vg + (size_t)row * SEQ + ch * 8);
    }
    CP_COMMIT();
}

__global__ __launch_bounds__(128) void attn_h(const int* __restrict__ cmask)
{
    __shared__ uint32_t Qs2[64 * ASTR2];
    __shared__ uint32_t Kst[2][64 * ASTR2];
    __shared__ uint32_t Vst[2][64 * ASTR2];   // Vt tile: [d][token]

    const int h   = blockIdx.y;
    const int it  = gridDim.x - 1 - blockIdx.x;   // big tiles first
    const int qi0 = it * 64;
    const int t    = threadIdx.x;
    const int warp = t >> 5;
    const int lane = t & 31;
    const int lr = lane >> 2;
    const int lc = lane & 3;
    const int w16 = warp * 16;
    const int lm16 = lane & 15;
    const int lk4  = (lane >> 4) * 4;
    const int causal = cmask ? cmask[0] : 1;

    const __half* kbase = g_K + (size_t)h * SEQ * HS;
    const __half* vbase = g_Vt + (size_t)h * HS * SEQ;
    const int jt_end = causal ? it : (SEQ / 64 - 1);

    kv_issue(Kst[0], Vst[0], kbase, vbase, 0, t);   // prefetch tile 0

    {   // Q tile (overlaps with cp.async in flight)
        const __half* src = g_Q + ((size_t)h * SEQ + qi0) * HS;
#pragma unroll
        for (int j = 0; j < 4; j++) {
            int idx = t + j * 128;
            int row = idx >> 3;
            int col = (idx & 7) * 8;
            *(uint4*)&Qs2[row * ASTR2 + col / 2] =
                *(const uint4*)(src + (size_t)row * HS + col);
        }
    }

    float mrow0 = -INFINITY, mrow1 = -INFINITY, l0 = 0.f, l1 = 0.f;
    float O[8][4];
#pragma unroll
    for (int nf = 0; nf < 8; nf++)
#pragma unroll
        for (int r = 0; r < 4; r++) O[nf][r] = 0.f;

    for (int jt = 0; jt <= jt_end; jt++) {
        const int s = jt & 1;
        __syncthreads();                 // all warps done with stage s^1 (jt-1)
        if (jt < jt_end) {
            kv_issue(Kst[s ^ 1], Vst[s ^ 1], kbase, vbase, jt + 1, t);
            CP_WAIT1();
        } else {
            CP_WAIT0();
        }
        __syncthreads();                 // stage s visible to all warps
        const uint32_t* Ks2 = Kst[s];
        const uint32_t* Vs2 = Vst[s];

        // ---- S' = (Q*0.125*log2e) K^T ----
        float c[8][4];
#pragma unroll
        for (int nf = 0; nf < 8; nf++)
#pragma unroll
            for (int r = 0; r < 4; r++) c[nf][r] = 0.f;

#pragma unroll
        for (int kk2 = 0; kk2 < 32; kk2 += 8) {
            uint32_t a0, a1, a2, a3;
            ldsm4(a0, a1, a2, a3,
                  s2u(&Qs2[(w16 + lm16) * ASTR2 + kk2 + lk4]));
#pragma unroll
            for (int nf2 = 0; nf2 < 4; nf2++) {
                uint32_t r0, r1, r2, r3;
                ldsm4(r0, r1, r2, r3,
                      s2u(&Ks2[(nf2 * 16 + lm16) * ASTR2 + kk2 + lk4]));
                mma16(c[2 * nf2    ], a0, a1, a2, a3, r0, r2);
                mma16(c[2 * nf2 + 1], a0, a1, a2, a3, r1, r3);
            }
        }

        // ---- causal mask (no scale needed — folded into Q) ----
        const bool diag = causal && (jt == it);
        if (diag) {
            const int row0 = qi0 + w16 + lr;
            const int row1 = row0 + 8;
#pragma unroll
            for (int nf = 0; nf < 8; nf++) {
                int col = jt * 64 + nf * 8 + 2 * lc;
                if (col     > row0) c[nf][0] = -INFINITY;
                if (col + 1 > row0) c[nf][1] = -INFINITY;
                if (col     > row1) c[nf][2] = -INFINITY;
                if (col + 1 > row1) c[nf][3] = -INFINITY;
            }
        }

        // ---- online softmax in log2 domain ----
        float mx0 = -INFINITY, mx1 = -INFINITY;
#pragma unroll
        for (int nf = 0; nf < 8; nf++) {
            mx0 = fmaxf(mx0, fmaxf(c[nf][0], c[nf][1]));
            mx1 = fmaxf(mx1, fmaxf(c[nf][2], c[nf][3]));
        }
        mx0 = fmaxf(mx0, __shfl_xor_sync(0xffffffffu, mx0, 1));
        mx0 = fmaxf(mx0, __shfl_xor_sync(0xffffffffu, mx0, 2));
        mx1 = fmaxf(mx1, __shfl_xor_sync(0xffffffffu, mx1, 1));
        mx1 = fmaxf(mx1, __shfl_xor_sync(0xffffffffu, mx1, 2));

        const float mn0 = fmaxf(mrow0, mx0);
        const float mn1 = fmaxf(mrow1, mx1);
        const float al0 = exp2f(mrow0 - mn0);
        const float al1 = exp2f(mrow1 - mn1);
        float s0 = 0.f, s1 = 0.f;
#pragma unroll
        for (int nf = 0; nf < 8; nf++) {
            c[nf][0] = exp2f(c[nf][0] - mn0); s0 += c[nf][0];
            c[nf][1] = exp2f(c[nf][1] - mn0); s0 += c[nf][1];
            c[nf][2] = exp2f(c[nf][2] - mn1); s1 += c[nf][2];
            c[nf][3] = exp2f(c[nf][3] - mn1); s1 += c[nf][3];
        }
        s0 += __shfl_xor_sync(0xffffffffu, s0, 1);
        s0 += __shfl_xor_sync(0xffffffffu, s0, 2);
        s1 += __shfl_xor_sync(0xffffffffu, s1, 1);
        s1 += __shfl_xor_sync(0xffffffffu, s1, 2);
        l0 = l0 * al0 + s0;  l1 = l1 * al1 + s1;
        mrow0 = mn0;         mrow1 = mn1;
#pragma unroll
        for (int nf = 0; nf < 8; nf++) {
            O[nf][0] *= al0; O[nf][1] *= al0;
            O[nf][2] *= al1; O[nf][3] *= al1;
        }

        // ---- O += P V, P straight from registers ----
#pragma unroll
        for (int k2 = 0; k2 < 4; k2++) {
            uint32_t a0 = packh2(c[2 * k2    ][0], c[2 * k2    ][1]);
            uint32_t a1 = packh2(c[2 * k2    ][2], c[2 * k2    ][3]);
            uint32_t a2 = packh2(c[2 * k2 + 1][0], c[2 * k2 + 1][1]);
            uint32_t a3 = packh2(c[2 * k2 + 1][2], c[2 * k2 + 1][3]);
#pragma unroll
            for (int nf2 = 0; nf2 < 4; nf2++) {
                uint32_t r0, r1, r2, r3;
                ldsm4(r0, r1, r2, r3,
                      s2u(&Vs2[(nf2 * 16 + lm16) * ASTR2 + 8 * k2 + lk4]));
                mma16(O[2 * nf2    ], a0, a1, a2, a3, r0, r2);
                mma16(O[2 * nf2 + 1], a0, a1, a2, a3, r1, r3);
            }
        }
    }

    // ---- epilogue: normalize, write fp16 to g_attn ----
    const float inv0 = 1.f / l0;
    const float inv1 = 1.f / l1;
#pragma unroll
    for (int nf = 0; nf < 8; nf++) {
        int col = h * HS + nf * 8 + 2 * lc;
        *(uint32_t*)&g_attn[(size_t)(qi0 + w16 + lr    ) * DMODEL + col] =
            packh2(O[nf][0] * inv0, O[nf][1] * inv0);
        *(uint32_t*)&g_attn[(size_t)(qi0 + w16 + lr + 8) * DMODEL + col] =
            packh2(O[nf][2] * inv1, O[nf][3] * inv1);
    }
}

// ---------------------------------------------------------------------------
extern "C" void kernel_launch(void* const* d_in, const int* in_sizes, int n_in,
                              void* d_out, int out_size)
{
    const float* x     = (const float*)d_in[0];
    const float* w_qkv = (const float*)d_in[1];
    const float* b_qkv = (const float*)d_in[2];
    const float* w_o   = (const float*)d_in[3];
    const float* b_o   = (const float*)d_in[4];
    const int*   cmask = (n_in > 5) ? (const int*)d_in[5] : nullptr;

    cudaFuncSetAttribute(gemm_h<0>,
                         cudaFuncAttributeMaxDynamicSharedMemorySize, GEMM_SMEM);
    cudaFuncSetAttribute(gemm_h<1>,
                         cudaFuncAttributeMaxDynamicSharedMemorySize, GEMM_SMEM);

    prepass<<<1024, 512>>>(x, w_qkv, w_o);
    gemm_h<0><<<dim3(3072 / 128, SEQ / 128), 256, GEMM_SMEM>>>(b_qkv, nullptr);
    attn_h<<<dim3(SEQ / 64, NH), 128>>>(cmask);
    gemm_h<1><<<dim3(DMODEL / 128, SEQ / 128), 256, GEMM_SMEM>>>(b_o,
                                                                 (float*)d_out);
}